// round 2
// baseline (speedup 1.0000x reference)
#include <cuda_runtime.h>
#include <math.h>

// Problem constants
#define NB 2
#define NS 2048
#define NHID 4096
#define NHEADS 32
#define HDIM 128
#define NQKV 12288   // 3*NHID
#define MTOK 4096    // NB*NS

// Scratch (device globals: allocation-free per harness rules)
__device__ float g_qkv[(size_t)MTOK * NQKV];               // 201 MB
__device__ float g_q[(size_t)NB * NHEADS * NS * HDIM];     // 67 MB, [b][h][s][d]
__device__ float g_k[(size_t)NB * NHEADS * NS * HDIM];
__device__ float g_v[(size_t)NB * NHEADS * NS * HDIM];
__device__ float g_att[(size_t)MTOK * NHID];               // 67 MB, [b*S+s][h*HD+d]

// ---------------------------------------------------------------------------
// GEMM (NT): C[m,n] = sum_k A[m,k] * Bw[n,k]
// 128x128 block tile, 256 threads, 8x8 microtile, K-tile = 16.
// M, N, K must be multiples of 128/128/16 (true for all call sites).
// ---------------------------------------------------------------------------
__global__ __launch_bounds__(256) void gemm_nt(
    const float* __restrict__ A, const float* __restrict__ Bw,
    float* __restrict__ C, int M, int N, int K)
{
    __shared__ float As[16][132];   // [k][m], padded stride
    __shared__ float Bs[16][132];   // [k][n]

    const int m0 = blockIdx.y * 128;
    const int n0 = blockIdx.x * 128;
    const int tid = threadIdx.x;
    const int tx = tid & 15;
    const int ty = tid >> 4;

    float acc[8][8];
#pragma unroll
    for (int i = 0; i < 8; i++)
#pragma unroll
        for (int j = 0; j < 8; j++) acc[i][j] = 0.f;

    for (int kk = 0; kk < K; kk += 16) {
        // Stage 128x16 of each operand, transposing to [k][m] layout.
#pragma unroll
        for (int i = 0; i < 2; i++) {
            int c  = tid + 256 * i;   // 0..511
            int m  = c >> 2;          // 0..127
            int kq = c & 3;           // 0..3  (k quad)
            float4 va = *(const float4*)(A  + (size_t)(m0 + m) * K + kk + kq * 4);
            As[kq*4+0][m] = va.x; As[kq*4+1][m] = va.y;
            As[kq*4+2][m] = va.z; As[kq*4+3][m] = va.w;
            float4 vb = *(const float4*)(Bw + (size_t)(n0 + m) * K + kk + kq * 4);
            Bs[kq*4+0][m] = vb.x; Bs[kq*4+1][m] = vb.y;
            Bs[kq*4+2][m] = vb.z; Bs[kq*4+3][m] = vb.w;
        }
        __syncthreads();

#pragma unroll
        for (int k = 0; k < 16; k++) {
            float a[8], b[8];
            *(float4*)(a)     = *(const float4*)&As[k][ty * 8];
            *(float4*)(a + 4) = *(const float4*)&As[k][ty * 8 + 4];
            *(float4*)(b)     = *(const float4*)&Bs[k][tx * 8];
            *(float4*)(b + 4) = *(const float4*)&Bs[k][tx * 8 + 4];
#pragma unroll
            for (int i = 0; i < 8; i++)
#pragma unroll
                for (int j = 0; j < 8; j++)
                    acc[i][j] = fmaf(a[i], b[j], acc[i][j]);
        }
        __syncthreads();
    }

#pragma unroll
    for (int i = 0; i < 8; i++) {
        int m = m0 + ty * 8 + i;
        float* dst = C + (size_t)m * N + n0 + tx * 8;
        *(float4*)(dst)     = make_float4(acc[i][0], acc[i][1], acc[i][2], acc[i][3]);
        *(float4*)(dst + 4) = make_float4(acc[i][4], acc[i][5], acc[i][6], acc[i][7]);
    }
}

// ---------------------------------------------------------------------------
// RoPE + split qkv into head-major Q/K/V: [b][h][s][d]
// One block per (b,s,h), 64 threads (one per rotation pair d, d+64).
// Angles computed in double to stay within 1e-4 of the fp32 reference.
// ---------------------------------------------------------------------------
__global__ __launch_bounds__(64) void rope_split(
    const float* __restrict__ qkv, const int* __restrict__ positions)
{
    int bidx = blockIdx.x;            // (b*NS + s)*NHEADS + h
    int h  = bidx % NHEADS;
    int ms = bidx / NHEADS;           // b*NS + s
    int s  = ms % NS;
    int b  = ms / NS;
    int d  = threadIdx.x;             // 0..63

    const float* row = qkv + (size_t)ms * NQKV + h * HDIM;

    double pos = (double)positions[ms];
    double inv = exp(-(double)d * (9.210340371976184 / 64.0));  // ln(10000)/64
    double ang = pos * inv;
    double sd, cd;
    sincos(ang, &sd, &cd);
    float sn = (float)sd, cs = (float)cd;

    float q1 = row[d],        q2 = row[d + 64];
    float k1 = row[NHID + d], k2 = row[NHID + d + 64];

    size_t o = ((size_t)(b * NHEADS + h) * NS + s) * HDIM + d;
    g_q[o]      = q1 * cs - q2 * sn;
    g_q[o + 64] = q2 * cs + q1 * sn;
    g_k[o]      = k1 * cs - k2 * sn;
    g_k[o + 64] = k2 * cs + k1 * sn;
    g_v[o]      = row[2 * NHID + d];
    g_v[o + 64] = row[2 * NHID + d + 64];
}

// ---------------------------------------------------------------------------
// Flash attention (causal), fp32. Grid: (S/64 q-tiles, B*NH). 256 threads.
// smem: Qs[128][68] (d-major) | KV union: Ks[128][68] / Vs[64][132] | Ps[64][68]
// ---------------------------------------------------------------------------
#define ATTN_SMEM_FLOATS (128*68 + 128*68 + 64*68)
#define ATTN_SMEM_BYTES  (ATTN_SMEM_FLOATS * 4)   // 87040

__global__ __launch_bounds__(256) void attn_kernel()
{
    extern __shared__ float sm[];
    float (*Qs)[68]  = (float(*)[68])sm;
    float* kvbuf     = sm + 128 * 68;
    float (*Ks)[68]  = (float(*)[68])kvbuf;
    float (*Vs)[132] = (float(*)[132])kvbuf;
    float (*Ps)[68]  = (float(*)[68])(kvbuf + 128 * 68);

    const int qt  = blockIdx.x;
    const int bh  = blockIdx.y;
    const int qs0 = qt * 64;
    const float* qb = g_q + (size_t)bh * NS * HDIM;
    const float* kb = g_k + (size_t)bh * NS * HDIM;
    const float* vb = g_v + (size_t)bh * NS * HDIM;

    const int tid = threadIdx.x;
    const int tx  = tid & 15;
    const int ty  = tid >> 4;
    const float scale = 0.08838834764831845f;   // 1/sqrt(128)

    // Load + scale Q tile (64 rows x 128 d) into d-major smem
#pragma unroll
    for (int i = 0; i < 8; i++) {
        int c = tid + 256 * i;          // 0..2047
        int r = c >> 5, dq = c & 31;
        float4 v = *(const float4*)(qb + (size_t)(qs0 + r) * HDIM + dq * 4);
        Qs[dq*4+0][r] = v.x * scale; Qs[dq*4+1][r] = v.y * scale;
        Qs[dq*4+2][r] = v.z * scale; Qs[dq*4+3][r] = v.w * scale;
    }

    float m_i[4], l_i[4], acc[4][8];
#pragma unroll
    for (int i = 0; i < 4; i++) {
        m_i[i] = -INFINITY;
        l_i[i] = 0.f;
#pragma unroll
        for (int j = 0; j < 8; j++) acc[i][j] = 0.f;
    }

    for (int kt = 0; kt <= qt; kt++) {
        const int ks0 = kt * 64;
        __syncthreads();   // prev PV done with Vs/Ps; Q visible on first iter

        // Load K tile (64 rows x 128 d) into d-major smem
#pragma unroll
        for (int i = 0; i < 8; i++) {
            int c = tid + 256 * i;
            int r = c >> 5, dq = c & 31;
            float4 v = *(const float4*)(kb + (size_t)(ks0 + r) * HDIM + dq * 4);
            Ks[dq*4+0][r] = v.x; Ks[dq*4+1][r] = v.y;
            Ks[dq*4+2][r] = v.z; Ks[dq*4+3][r] = v.w;
        }
        __syncthreads();

        // Scores: S[64][64] = Qs^T * Ks, 4x4 per thread
        float s[4][4];
#pragma unroll
        for (int i = 0; i < 4; i++)
#pragma unroll
            for (int j = 0; j < 4; j++) s[i][j] = 0.f;

#pragma unroll 8
        for (int d = 0; d < 128; d++) {
            float a[4], b[4];
            *(float4*)a = *(const float4*)&Qs[d][ty * 4];
            *(float4*)b = *(const float4*)&Ks[d][tx * 4];
#pragma unroll
            for (int i = 0; i < 4; i++)
#pragma unroll
                for (int j = 0; j < 4; j++)
                    s[i][j] = fmaf(a[i], b[j], s[i][j]);
        }

        if (kt == qt) {   // diagonal tile: causal mask
#pragma unroll
            for (int i = 0; i < 4; i++)
#pragma unroll
                for (int j = 0; j < 4; j++)
                    if (tx * 4 + j > ty * 4 + i) s[i][j] = -1e30f;
        }

        // Online softmax (rows owned by 16 lanes with same ty)
#pragma unroll
        for (int i = 0; i < 4; i++) {
            float mx = fmaxf(fmaxf(s[i][0], s[i][1]), fmaxf(s[i][2], s[i][3]));
            mx = fmaxf(mx, __shfl_xor_sync(0xffffffffu, mx, 8));
            mx = fmaxf(mx, __shfl_xor_sync(0xffffffffu, mx, 4));
            mx = fmaxf(mx, __shfl_xor_sync(0xffffffffu, mx, 2));
            mx = fmaxf(mx, __shfl_xor_sync(0xffffffffu, mx, 1));

            float mnew = fmaxf(m_i[i], mx);
            float corr = __expf(m_i[i] - mnew);
            float rs = 0.f;
#pragma unroll
            for (int j = 0; j < 4; j++) {
                float p = __expf(s[i][j] - mnew);
                s[i][j] = p;
                rs += p;
            }
            rs += __shfl_xor_sync(0xffffffffu, rs, 8);
            rs += __shfl_xor_sync(0xffffffffu, rs, 4);
            rs += __shfl_xor_sync(0xffffffffu, rs, 2);
            rs += __shfl_xor_sync(0xffffffffu, rs, 1);

            l_i[i] = l_i[i] * corr + rs;
            m_i[i] = mnew;
#pragma unroll
            for (int j = 0; j < 8; j++) acc[i][j] *= corr;
#pragma unroll
            for (int j = 0; j < 4; j++)
                Ps[tx * 4 + j][ty * 4 + i] = s[i][j];   // kc-major P
        }
        __syncthreads();   // P written; Ks reads finished

        // Load V tile (64 rows x 128 d) into kc-major smem (natural layout)
#pragma unroll
        for (int i = 0; i < 8; i++) {
            int c = tid + 256 * i;
            int r = c >> 5, dq = c & 31;
            *(float4*)&Vs[r][dq * 4] =
                *(const float4*)(vb + (size_t)(ks0 + r) * HDIM + dq * 4);
        }
        __syncthreads();

        // O[64][128] += P[64][64] * V[64][128]; 4 rows x 8 cols per thread
#pragma unroll 4
        for (int kc = 0; kc < 64; kc++) {
            float p[4], v0[8];
            *(float4*)p        = *(const float4*)&Ps[kc][ty * 4];
            *(float4*)(v0)     = *(const float4*)&Vs[kc][tx * 8];
            *(float4*)(v0 + 4) = *(const float4*)&Vs[kc][tx * 8 + 4];
#pragma unroll
            for (int i = 0; i < 4; i++)
#pragma unroll
                for (int j = 0; j < 8; j++)
                    acc[i][j] = fmaf(p[i], v0[j], acc[i][j]);
        }
    }

    // Epilogue: normalize and scatter to [b*S+s][h*HD+d]
    const int b = bh >> 5;        // bh / NHEADS
    const int h = bh & 31;        // bh % NHEADS
#pragma unroll
    for (int i = 0; i < 4; i++) {
        float inv = 1.f / l_i[i];
        int srow = qs0 + ty * 4 + i;
        float* dst = g_att + (size_t)(b * NS + srow) * NHID + h * HDIM + tx * 8;
        *(float4*)(dst)     = make_float4(acc[i][0]*inv, acc[i][1]*inv, acc[i][2]*inv, acc[i][3]*inv);
        *(float4*)(dst + 4) = make_float4(acc[i][4]*inv, acc[i][5]*inv, acc[i][6]*inv, acc[i][7]*inv);
    }
}

// ---------------------------------------------------------------------------
// Launch
// ---------------------------------------------------------------------------
extern "C" void kernel_launch(void* const* d_in, const int* in_sizes, int n_in,
                              void* d_out, int out_size)
{
    const float* hs  = (const float*)d_in[0];   // [B,S,H]
    const int*   pos = (const int*)  d_in[1];   // [B,S]
    const float* wp  = (const float*)d_in[2];   // [3H,H]
    const float* wo  = (const float*)d_in[3];   // [H,H]
    float* out = (float*)d_out;                 // [B,S,H]

    float* qkv; cudaGetSymbolAddress((void**)&qkv, g_qkv);
    float* att; cudaGetSymbolAddress((void**)&att, g_att);

    // 1. QKV projection: [4096,4096] x [12288,4096]^T
    gemm_nt<<<dim3(NQKV / 128, MTOK / 128), 256>>>(hs, wp, qkv, MTOK, NQKV, NHID);

    // 2. RoPE + head-major split
    rope_split<<<NB * NS * NHEADS, 64>>>(qkv, pos);

    // 3. Causal flash attention
    cudaFuncSetAttribute(attn_kernel, cudaFuncAttributeMaxDynamicSharedMemorySize,
                         ATTN_SMEM_BYTES);
    attn_kernel<<<dim3(NS / 64, NB * NHEADS), 256, ATTN_SMEM_BYTES>>>();

    // 4. Output projection: [4096,4096] x [4096,4096]^T
    gemm_nt<<<dim3(NHID / 128, MTOK / 128), 256>>>(att, wo, out, MTOK, NHID, NHID);
}

// round 4
// speedup vs baseline: 1.8272x; 1.8272x over previous
#include <cuda_runtime.h>
#include <cuda_bf16.h>
#include <math.h>
#include <stdint.h>

// Problem constants
#define NB 2
#define NS 2048
#define NHID 4096
#define NHEADS 32
#define HDIM 128
#define NQKV 12288   // 3*NHID
#define MTOK 4096    // NB*NS

// Scratch (device globals: allocation-free per harness rules)
__device__ float g_qkv[(size_t)MTOK * NQKV];               // 201 MB
__device__ float g_q[(size_t)NB * NHEADS * NS * HDIM];     // 67 MB, [b][h][s][d]
__device__ float g_k[(size_t)NB * NHEADS * NS * HDIM];
__device__ float g_v[(size_t)NB * NHEADS * NS * HDIM];
__device__ float g_att[(size_t)MTOK * NHID];               // 67 MB
__device__ __nv_bfloat16 g_ahi[(size_t)MTOK * NHID];       // 33.5 MB
__device__ __nv_bfloat16 g_alo[(size_t)MTOK * NHID];
__device__ __nv_bfloat16 g_bhi[(size_t)NQKV * NHID];       // 100 MB
__device__ __nv_bfloat16 g_blo[(size_t)NQKV * NHID];

// ---------------------------------------------------------------------------
// Helpers: cp.async, ldmatrix, mma (all valid on compute_100 baseline PTX)
// ---------------------------------------------------------------------------
__device__ __forceinline__ uint32_t smem_u32(const void* p) {
    uint32_t a;
    asm("{ .reg .u64 t; cvta.to.shared.u64 t, %1; cvt.u32.u64 %0, t; }"
        : "=r"(a) : "l"(p));
    return a;
}

__device__ __forceinline__ void cp_async16(uint32_t dst, const void* src) {
    asm volatile("cp.async.cg.shared.global [%0], [%1], 16;" :: "r"(dst), "l"(src));
}
#define CP_COMMIT() asm volatile("cp.async.commit_group;" ::: "memory")

__device__ __forceinline__ void ldsm4(uint32_t* r, uint32_t addr) {
    asm volatile("ldmatrix.sync.aligned.m8n8.x4.shared.b16 {%0,%1,%2,%3}, [%4];"
                 : "=r"(r[0]), "=r"(r[1]), "=r"(r[2]), "=r"(r[3]) : "r"(addr));
}

__device__ __forceinline__ void mma16816(float* c, const uint32_t* a,
                                         uint32_t b0, uint32_t b1) {
    asm volatile(
        "mma.sync.aligned.m16n8k16.row.col.f32.bf16.bf16.f32 "
        "{%0,%1,%2,%3}, {%4,%5,%6,%7}, {%8,%9}, {%0,%1,%2,%3};"
        : "+f"(c[0]), "+f"(c[1]), "+f"(c[2]), "+f"(c[3])
        : "r"(a[0]), "r"(a[1]), "r"(a[2]), "r"(a[3]), "r"(b0), "r"(b1));
}

#define SWZ(x) ((x) ^ (((x) >> 3) & 0x70))   // SW128: conflict-free ldmatrix

// ---------------------------------------------------------------------------
// split: x (fp32) -> hi + lo (bf16 each)
// ---------------------------------------------------------------------------
__global__ __launch_bounds__(256) void split_bf16(
    const float* __restrict__ x, __nv_bfloat16* __restrict__ hi,
    __nv_bfloat16* __restrict__ lo)
{
    size_t i = ((size_t)blockIdx.x * 256 + threadIdx.x) * 4;
    float4 v = *(const float4*)(x + i);
    __nv_bfloat16 h0 = __float2bfloat16_rn(v.x);
    __nv_bfloat16 h1 = __float2bfloat16_rn(v.y);
    __nv_bfloat16 h2 = __float2bfloat16_rn(v.z);
    __nv_bfloat16 h3 = __float2bfloat16_rn(v.w);
    __nv_bfloat16 l0 = __float2bfloat16_rn(v.x - __bfloat162float(h0));
    __nv_bfloat16 l1 = __float2bfloat16_rn(v.y - __bfloat162float(h1));
    __nv_bfloat16 l2 = __float2bfloat16_rn(v.z - __bfloat162float(h2));
    __nv_bfloat16 l3 = __float2bfloat16_rn(v.w - __bfloat162float(h3));
    *(__nv_bfloat162*)(hi + i)     = __nv_bfloat162(h0, h1);
    *(__nv_bfloat162*)(hi + i + 2) = __nv_bfloat162(h2, h3);
    *(__nv_bfloat162*)(lo + i)     = __nv_bfloat162(l0, l1);
    *(__nv_bfloat162*)(lo + i + 2) = __nv_bfloat162(l2, l3);
}

// ---------------------------------------------------------------------------
// bf16 split GEMM (NT): C[m,n] = sum_k A[m,k]*B[n,k]
//   = Ahi*Bhi + Ahi*Blo + Alo*Bhi  (lo*lo dropped; ~1e-5 rel err)
// CTA 128x128, 8 warps (2m x 4n), warp tile 64x32, KTILE=32,
// double-buffered cp.async. smem row = 128B: [hi k0..31 | lo k0..31], SW128.
// ---------------------------------------------------------------------------
#define BKT 32
#define ABUF 16384                  // 128 rows x 128 B
#define STG  (2 * ABUF)             // A + B
#define GEMM_SMEM (2 * STG)         // double buffer: 64 KB

__global__ __launch_bounds__(256, 1) void gemm_bf16(
    const __nv_bfloat16* __restrict__ Ahi, const __nv_bfloat16* __restrict__ Alo,
    const __nv_bfloat16* __restrict__ Bhi, const __nv_bfloat16* __restrict__ Blo,
    float* __restrict__ C, int M, int N, int K)
{
    extern __shared__ char smem[];
    const uint32_t sbase = smem_u32(smem);

    const int tid  = threadIdx.x;
    const int lane = tid & 31;
    const int wid  = tid >> 5;
    const int wm   = wid >> 2;          // 0..1
    const int wn   = wid & 3;           // 0..3
    const int m0   = blockIdx.x * 128;
    const int n0   = blockIdx.y * 128;

    // cp.async tile loader: 2048 16B chunks, 8 per thread
    auto load_stage = [&](int kt, int st) {
        const int kk = kt * BKT;
        const uint32_t su = sbase + st * STG;
#pragma unroll
        for (int i = 0; i < 8; i++) {
            int c   = tid + 256 * i;        // 0..2047
            int op  = c >> 10;              // 0=A, 1=B
            int rem = c & 1023;
            int r   = rem >> 3;             // row 0..127
            int ch  = rem & 7;              // chunk: 0-3 hi, 4-7 lo
            int p   = ch >> 2;
            int c4  = ch & 3;
            uint32_t dst = su + op * ABUF + SWZ((uint32_t)(r * 128 + ch * 16));
            const __nv_bfloat16* src =
                op ? (p ? Blo : Bhi) : (p ? Alo : Ahi);
            size_t g = (size_t)((op ? n0 : m0) + r) * K + kk + c4 * 8;
            cp_async16(dst, src + g);
        }
        CP_COMMIT();
    };

    float acc[4][4][4];
#pragma unroll
    for (int i = 0; i < 4; i++)
#pragma unroll
        for (int j = 0; j < 4; j++)
#pragma unroll
            for (int v = 0; v < 4; v++) acc[i][j][v] = 0.f;

    const int KT = K / BKT;
    load_stage(0, 0);

    // per-lane ldmatrix base indices (x4 layout: mat = lane>>3)
    const int mat  = lane >> 3;
    const int rsub = (mat & 1) * 8 + (lane & 7);   // row within 16-row frag
    const int csub = mat >> 1;                     // 16B chunk within k16

    for (int kt = 0; kt < KT; kt++) {
        if (kt + 1 < KT) {
            load_stage(kt + 1, (kt + 1) & 1);
            asm volatile("cp.async.wait_group 1;" ::: "memory");
        } else {
            asm volatile("cp.async.wait_group 0;" ::: "memory");
        }
        __syncthreads();

        const uint32_t Ab = sbase + (kt & 1) * STG;
        const uint32_t Bb = Ab + ABUF;

#pragma unroll
        for (int ks = 0; ks < 2; ks++) {
            uint32_t ah[4][4], al[4][4], bh[2][4], bl[2][4];
#pragma unroll
            for (int mf = 0; mf < 4; mf++) {
                int r = wm * 64 + mf * 16 + rsub;
                int chh = ks * 2 + csub;
                ldsm4(ah[mf], Ab + SWZ((uint32_t)(r * 128 + chh * 16)));
                ldsm4(al[mf], Ab + SWZ((uint32_t)(r * 128 + (chh + 4) * 16)));
            }
#pragma unroll
            for (int nf2 = 0; nf2 < 2; nf2++) {
                int r = wn * 32 + nf2 * 16 + rsub;
                int chh = ks * 2 + csub;
                ldsm4(bh[nf2], Bb + SWZ((uint32_t)(r * 128 + chh * 16)));
                ldsm4(bl[nf2], Bb + SWZ((uint32_t)(r * 128 + (chh + 4) * 16)));
            }
#pragma unroll
            for (int mf = 0; mf < 4; mf++)
#pragma unroll
                for (int nf = 0; nf < 4; nf++) {
                    uint32_t bh0 = bh[nf >> 1][nf & 1], bh1 = bh[nf >> 1][(nf & 1) + 2];
                    uint32_t bl0 = bl[nf >> 1][nf & 1], bl1 = bl[nf >> 1][(nf & 1) + 2];
                    mma16816(acc[mf][nf], ah[mf], bh0, bh1);
                    mma16816(acc[mf][nf], ah[mf], bl0, bl1);
                    mma16816(acc[mf][nf], al[mf], bh0, bh1);
                }
        }
        __syncthreads();
    }

    // Epilogue: register fragments -> gmem (float2 per half-tile)
    const int g  = lane >> 2;
    const int tq = lane & 3;
#pragma unroll
    for (int mf = 0; mf < 4; mf++) {
#pragma unroll
        for (int nf = 0; nf < 4; nf++) {
            int row = m0 + wm * 64 + mf * 16 + g;
            int col = n0 + wn * 32 + nf * 8 + tq * 2;
            *(float2*)(C + (size_t)row * N + col) =
                make_float2(acc[mf][nf][0], acc[mf][nf][1]);
            *(float2*)(C + (size_t)(row + 8) * N + col) =
                make_float2(acc[mf][nf][2], acc[mf][nf][3]);
        }
    }
}

// ---------------------------------------------------------------------------
// RoPE + split qkv into head-major Q/K/V: [b][h][s][d]
// ---------------------------------------------------------------------------
__global__ __launch_bounds__(64) void rope_split(
    const float* __restrict__ qkv, const int* __restrict__ positions)
{
    int bidx = blockIdx.x;
    int h  = bidx % NHEADS;
    int ms = bidx / NHEADS;
    int s  = ms % NS;
    int b  = ms / NS;
    int d  = threadIdx.x;

    const float* row = qkv + (size_t)ms * NQKV + h * HDIM;

    double pos = (double)positions[ms];
    double inv = exp(-(double)d * (9.210340371976184 / 64.0));
    double ang = pos * inv;
    double sd, cd;
    sincos(ang, &sd, &cd);
    float sn = (float)sd, cs = (float)cd;

    float q1 = row[d],        q2 = row[d + 64];
    float k1 = row[NHID + d], k2 = row[NHID + d + 64];

    size_t o = ((size_t)(b * NHEADS + h) * NS + s) * HDIM + d;
    g_q[o]      = q1 * cs - q2 * sn;
    g_q[o + 64] = q2 * cs + q1 * sn;
    g_k[o]      = k1 * cs - k2 * sn;
    g_k[o + 64] = k2 * cs + k1 * sn;
    g_v[o]      = row[2 * NHID + d];
    g_v[o + 64] = row[2 * NHID + d + 64];
}

// ---------------------------------------------------------------------------
// Flash attention (causal), fp32 (unchanged, correct)
// ---------------------------------------------------------------------------
#define ATTN_SMEM_FLOATS (128*68 + 128*68 + 64*68)
#define ATTN_SMEM_BYTES  (ATTN_SMEM_FLOATS * 4)

__global__ __launch_bounds__(256) void attn_kernel()
{
    extern __shared__ float sm[];
    float (*Qs)[68]  = (float(*)[68])sm;
    float* kvbuf     = sm + 128 * 68;
    float (*Ks)[68]  = (float(*)[68])kvbuf;
    float (*Vs)[132] = (float(*)[132])kvbuf;
    float (*Ps)[68]  = (float(*)[68])(kvbuf + 128 * 68);

    const int qt  = blockIdx.x;
    const int bh  = blockIdx.y;
    const int qs0 = qt * 64;
    const float* qb = g_q + (size_t)bh * NS * HDIM;
    const float* kb = g_k + (size_t)bh * NS * HDIM;
    const float* vb = g_v + (size_t)bh * NS * HDIM;

    const int tid = threadIdx.x;
    const int tx  = tid & 15;
    const int ty  = tid >> 4;
    const float scale = 0.08838834764831845f;

#pragma unroll
    for (int i = 0; i < 8; i++) {
        int c = tid + 256 * i;
        int r = c >> 5, dq = c & 31;
        float4 v = *(const float4*)(qb + (size_t)(qs0 + r) * HDIM + dq * 4);
        Qs[dq*4+0][r] = v.x * scale; Qs[dq*4+1][r] = v.y * scale;
        Qs[dq*4+2][r] = v.z * scale; Qs[dq*4+3][r] = v.w * scale;
    }

    float m_i[4], l_i[4], acc[4][8];
#pragma unroll
    for (int i = 0; i < 4; i++) {
        m_i[i] = -INFINITY;
        l_i[i] = 0.f;
#pragma unroll
        for (int j = 0; j < 8; j++) acc[i][j] = 0.f;
    }

    for (int kt = 0; kt <= qt; kt++) {
        const int ks0 = kt * 64;
        __syncthreads();

#pragma unroll
        for (int i = 0; i < 8; i++) {
            int c = tid + 256 * i;
            int r = c >> 5, dq = c & 31;
            float4 v = *(const float4*)(kb + (size_t)(ks0 + r) * HDIM + dq * 4);
            Ks[dq*4+0][r] = v.x; Ks[dq*4+1][r] = v.y;
            Ks[dq*4+2][r] = v.z; Ks[dq*4+3][r] = v.w;
        }
        __syncthreads();

        float s[4][4];
#pragma unroll
        for (int i = 0; i < 4; i++)
#pragma unroll
            for (int j = 0; j < 4; j++) s[i][j] = 0.f;

#pragma unroll 8
        for (int d = 0; d < 128; d++) {
            float a[4], b[4];
            *(float4*)a = *(const float4*)&Qs[d][ty * 4];
            *(float4*)b = *(const float4*)&Ks[d][tx * 4];
#pragma unroll
            for (int i = 0; i < 4; i++)
#pragma unroll
                for (int j = 0; j < 4; j++)
                    s[i][j] = fmaf(a[i], b[j], s[i][j]);
        }

        if (kt == qt) {
#pragma unroll
            for (int i = 0; i < 4; i++)
#pragma unroll
                for (int j = 0; j < 4; j++)
                    if (tx * 4 + j > ty * 4 + i) s[i][j] = -1e30f;
        }

#pragma unroll
        for (int i = 0; i < 4; i++) {
            float mx = fmaxf(fmaxf(s[i][0], s[i][1]), fmaxf(s[i][2], s[i][3]));
            mx = fmaxf(mx, __shfl_xor_sync(0xffffffffu, mx, 8));
            mx = fmaxf(mx, __shfl_xor_sync(0xffffffffu, mx, 4));
            mx = fmaxf(mx, __shfl_xor_sync(0xffffffffu, mx, 2));
            mx = fmaxf(mx, __shfl_xor_sync(0xffffffffu, mx, 1));

            float mnew = fmaxf(m_i[i], mx);
            float corr = __expf(m_i[i] - mnew);
            float rs = 0.f;
#pragma unroll
            for (int j = 0; j < 4; j++) {
                float p = __expf(s[i][j] - mnew);
                s[i][j] = p;
                rs += p;
            }
            rs += __shfl_xor_sync(0xffffffffu, rs, 8);
            rs += __shfl_xor_sync(0xffffffffu, rs, 4);
            rs += __shfl_xor_sync(0xffffffffu, rs, 2);
            rs += __shfl_xor_sync(0xffffffffu, rs, 1);

            l_i[i] = l_i[i] * corr + rs;
            m_i[i] = mnew;
#pragma unroll
            for (int j = 0; j < 8; j++) acc[i][j] *= corr;
#pragma unroll
            for (int j = 0; j < 4; j++)
                Ps[tx * 4 + j][ty * 4 + i] = s[i][j];
        }
        __syncthreads();

#pragma unroll
        for (int i = 0; i < 8; i++) {
            int c = tid + 256 * i;
            int r = c >> 5, dq = c & 31;
            *(float4*)&Vs[r][dq * 4] =
                *(const float4*)(vb + (size_t)(ks0 + r) * HDIM + dq * 4);
        }
        __syncthreads();

#pragma unroll 4
        for (int kc = 0; kc < 64; kc++) {
            float p[4], v0[8];
            *(float4*)p        = *(const float4*)&Ps[kc][ty * 4];
            *(float4*)(v0)     = *(const float4*)&Vs[kc][tx * 8];
            *(float4*)(v0 + 4) = *(const float4*)&Vs[kc][tx * 8 + 4];
#pragma unroll
            for (int i = 0; i < 4; i++)
#pragma unroll
                for (int j = 0; j < 8; j++)
                    acc[i][j] = fmaf(p[i], v0[j], acc[i][j]);
        }
    }

    const int b = bh >> 5;
    const int h = bh & 31;
#pragma unroll
    for (int i = 0; i < 4; i++) {
        float inv = 1.f / l_i[i];
        int srow = qs0 + ty * 4 + i;
        float* dst = g_att + (size_t)(b * NS + srow) * NHID + h * HDIM + tx * 8;
        *(float4*)(dst)     = make_float4(acc[i][0]*inv, acc[i][1]*inv, acc[i][2]*inv, acc[i][3]*inv);
        *(float4*)(dst + 4) = make_float4(acc[i][4]*inv, acc[i][5]*inv, acc[i][6]*inv, acc[i][7]*inv);
    }
}

// ---------------------------------------------------------------------------
// Launch
// ---------------------------------------------------------------------------
extern "C" void kernel_launch(void* const* d_in, const int* in_sizes, int n_in,
                              void* d_out, int out_size)
{
    const float* hs  = (const float*)d_in[0];   // [B,S,H]
    const int*   pos = (const int*)  d_in[1];   // [B,S]
    const float* wp  = (const float*)d_in[2];   // [3H,H]
    const float* wo  = (const float*)d_in[3];   // [H,H]
    float* out = (float*)d_out;                 // [B,S,H]

    float* qkv; cudaGetSymbolAddress((void**)&qkv, g_qkv);
    float* att; cudaGetSymbolAddress((void**)&att, g_att);
    __nv_bfloat16 *ahi, *alo, *bhi, *blo;
    cudaGetSymbolAddress((void**)&ahi, g_ahi);
    cudaGetSymbolAddress((void**)&alo, g_alo);
    cudaGetSymbolAddress((void**)&bhi, g_bhi);
    cudaGetSymbolAddress((void**)&blo, g_blo);

    cudaFuncSetAttribute(gemm_bf16, cudaFuncAttributeMaxDynamicSharedMemorySize, GEMM_SMEM);
    cudaFuncSetAttribute(attn_kernel, cudaFuncAttributeMaxDynamicSharedMemorySize,
                         ATTN_SMEM_BYTES);

    // 1. split inputs to bf16 hi/lo
    split_bf16<<<(size_t)MTOK * NHID / 1024, 256>>>(hs, ahi, alo);
    split_bf16<<<(size_t)NQKV * NHID / 1024, 256>>>(wp, bhi, blo);

    // 2. QKV projection (tensor cores): [4096,4096] x [12288,4096]^T
    gemm_bf16<<<dim3(MTOK / 128, NQKV / 128), 256, GEMM_SMEM>>>(
        ahi, alo, bhi, blo, qkv, MTOK, NQKV, NHID);

    // 3. RoPE + head-major split
    rope_split<<<NB * NS * NHEADS, 64>>>(qkv, pos);

    // 4. Causal flash attention
    attn_kernel<<<dim3(NS / 64, NB * NHEADS), 256, ATTN_SMEM_BYTES>>>();

    // 5. split attention output + w_o, then output projection
    split_bf16<<<(size_t)MTOK * NHID / 1024, 256>>>(att, ahi, alo);
    split_bf16<<<(size_t)NHID * NHID / 1024, 256>>>(wo, bhi, blo);
    gemm_bf16<<<dim3(MTOK / 128, NHID / 128), 256, GEMM_SMEM>>>(
        ahi, alo, bhi, blo, out, MTOK, NHID, NHID);
}

// round 5
// speedup vs baseline: 2.6621x; 1.4569x over previous
#include <cuda_runtime.h>
#include <cuda_bf16.h>
#include <math.h>
#include <stdint.h>

// Problem constants
#define NB 2
#define NS 2048
#define NHID 4096
#define NHEADS 32
#define HDIM 128
#define NQKV 12288   // 3*NHID
#define MTOK 4096    // NB*NS

// Scratch (device globals: allocation-free per harness rules)
__device__ float g_qkv[(size_t)MTOK * NQKV];               // 201 MB
__device__ __nv_bfloat16 g_qb [(size_t)NB * NHEADS * NS * HDIM];  // bf16, q*scale
__device__ __nv_bfloat16 g_kb [(size_t)NB * NHEADS * NS * HDIM];
__device__ __nv_bfloat16 g_vhi[(size_t)NB * NHEADS * NS * HDIM];
__device__ __nv_bfloat16 g_vlo[(size_t)NB * NHEADS * NS * HDIM];
__device__ __nv_bfloat16 g_ahi[(size_t)MTOK * NHID];       // GEMM A hi
__device__ __nv_bfloat16 g_alo[(size_t)MTOK * NHID];
__device__ __nv_bfloat16 g_bhi[(size_t)NQKV * NHID];       // GEMM B hi
__device__ __nv_bfloat16 g_blo[(size_t)NQKV * NHID];

// ---------------------------------------------------------------------------
// Helpers (baseline PTX, valid on compute_100)
// ---------------------------------------------------------------------------
__device__ __forceinline__ uint32_t smem_u32(const void* p) {
    uint32_t a;
    asm("{ .reg .u64 t; cvta.to.shared.u64 t, %1; cvt.u32.u64 %0, t; }"
        : "=r"(a) : "l"(p));
    return a;
}

__device__ __forceinline__ void cp_async16(uint32_t dst, const void* src) {
    asm volatile("cp.async.cg.shared.global [%0], [%1], 16;" :: "r"(dst), "l"(src));
}
#define CP_COMMIT() asm volatile("cp.async.commit_group;" ::: "memory")

__device__ __forceinline__ void ldsm4(uint32_t* r, uint32_t addr) {
    asm volatile("ldmatrix.sync.aligned.m8n8.x4.shared.b16 {%0,%1,%2,%3}, [%4];"
                 : "=r"(r[0]), "=r"(r[1]), "=r"(r[2]), "=r"(r[3]) : "r"(addr));
}
__device__ __forceinline__ void ldsm4t(uint32_t* r, uint32_t addr) {
    asm volatile("ldmatrix.sync.aligned.m8n8.x4.trans.shared.b16 {%0,%1,%2,%3}, [%4];"
                 : "=r"(r[0]), "=r"(r[1]), "=r"(r[2]), "=r"(r[3]) : "r"(addr));
}

__device__ __forceinline__ void mma16816(float* c, const uint32_t* a,
                                         uint32_t b0, uint32_t b1) {
    asm volatile(
        "mma.sync.aligned.m16n8k16.row.col.f32.bf16.bf16.f32 "
        "{%0,%1,%2,%3}, {%4,%5,%6,%7}, {%8,%9}, {%0,%1,%2,%3};"
        : "+f"(c[0]), "+f"(c[1]), "+f"(c[2]), "+f"(c[3])
        : "r"(a[0]), "r"(a[1]), "r"(a[2]), "r"(a[3]), "r"(b0), "r"(b1));
}

#define SWZ(x) ((x) ^ (((x) >> 3) & 0x70))   // 128B rows (GEMM)

__device__ __forceinline__ uint32_t pack_bf16(float x, float y) {
    __nv_bfloat162 t(__float2bfloat16_rn(x), __float2bfloat16_rn(y));
    return *(uint32_t*)&t;
}

// ---------------------------------------------------------------------------
// split: x (fp32) -> hi + lo (bf16 each)
// ---------------------------------------------------------------------------
__global__ __launch_bounds__(256) void split_bf16(
    const float* __restrict__ x, __nv_bfloat16* __restrict__ hi,
    __nv_bfloat16* __restrict__ lo)
{
    size_t i = ((size_t)blockIdx.x * 256 + threadIdx.x) * 4;
    float4 v = *(const float4*)(x + i);
    __nv_bfloat16 h0 = __float2bfloat16_rn(v.x);
    __nv_bfloat16 h1 = __float2bfloat16_rn(v.y);
    __nv_bfloat16 h2 = __float2bfloat16_rn(v.z);
    __nv_bfloat16 h3 = __float2bfloat16_rn(v.w);
    __nv_bfloat16 l0 = __float2bfloat16_rn(v.x - __bfloat162float(h0));
    __nv_bfloat16 l1 = __float2bfloat16_rn(v.y - __bfloat162float(h1));
    __nv_bfloat16 l2 = __float2bfloat16_rn(v.z - __bfloat162float(h2));
    __nv_bfloat16 l3 = __float2bfloat16_rn(v.w - __bfloat162float(h3));
    *(__nv_bfloat162*)(hi + i)     = __nv_bfloat162(h0, h1);
    *(__nv_bfloat162*)(hi + i + 2) = __nv_bfloat162(h2, h3);
    *(__nv_bfloat162*)(lo + i)     = __nv_bfloat162(l0, l1);
    *(__nv_bfloat162*)(lo + i + 2) = __nv_bfloat162(l2, l3);
}

// ---------------------------------------------------------------------------
// bf16 split GEMM (NT) — unchanged from R4 (passing, ~300 TF/s)
// ---------------------------------------------------------------------------
#define BKT 32
#define ABUF 16384
#define STG  (2 * ABUF)
#define GEMM_SMEM (2 * STG)

__global__ __launch_bounds__(256, 1) void gemm_bf16(
    const __nv_bfloat16* __restrict__ Ahi, const __nv_bfloat16* __restrict__ Alo,
    const __nv_bfloat16* __restrict__ Bhi, const __nv_bfloat16* __restrict__ Blo,
    float* __restrict__ C, int M, int N, int K)
{
    extern __shared__ char smem[];
    const uint32_t sbase = smem_u32(smem);

    const int tid  = threadIdx.x;
    const int lane = tid & 31;
    const int wid  = tid >> 5;
    const int wm   = wid >> 2;
    const int wn   = wid & 3;
    const int m0   = blockIdx.x * 128;
    const int n0   = blockIdx.y * 128;

    auto load_stage = [&](int kt, int st) {
        const int kk = kt * BKT;
        const uint32_t su = sbase + st * STG;
#pragma unroll
        for (int i = 0; i < 8; i++) {
            int c   = tid + 256 * i;
            int op  = c >> 10;
            int rem = c & 1023;
            int r   = rem >> 3;
            int ch  = rem & 7;
            int p   = ch >> 2;
            int c4  = ch & 3;
            uint32_t dst = su + op * ABUF + SWZ((uint32_t)(r * 128 + ch * 16));
            const __nv_bfloat16* src =
                op ? (p ? Blo : Bhi) : (p ? Alo : Ahi);
            size_t gaddr = (size_t)((op ? n0 : m0) + r) * K + kk + c4 * 8;
            cp_async16(dst, src + gaddr);
        }
        CP_COMMIT();
    };

    float acc[4][4][4];
#pragma unroll
    for (int i = 0; i < 4; i++)
#pragma unroll
        for (int j = 0; j < 4; j++)
#pragma unroll
            for (int v = 0; v < 4; v++) acc[i][j][v] = 0.f;

    const int KT = K / BKT;
    load_stage(0, 0);

    const int mat  = lane >> 3;
    const int rsub = (mat & 1) * 8 + (lane & 7);
    const int csub = mat >> 1;

    for (int kt = 0; kt < KT; kt++) {
        if (kt + 1 < KT) {
            load_stage(kt + 1, (kt + 1) & 1);
            asm volatile("cp.async.wait_group 1;" ::: "memory");
        } else {
            asm volatile("cp.async.wait_group 0;" ::: "memory");
        }
        __syncthreads();

        const uint32_t Ab = sbase + (kt & 1) * STG;
        const uint32_t Bb = Ab + ABUF;

#pragma unroll
        for (int ks = 0; ks < 2; ks++) {
            uint32_t ah[4][4], al[4][4], bh[2][4], bl[2][4];
#pragma unroll
            for (int mf = 0; mf < 4; mf++) {
                int r = wm * 64 + mf * 16 + rsub;
                int chh = ks * 2 + csub;
                ldsm4(ah[mf], Ab + SWZ((uint32_t)(r * 128 + chh * 16)));
                ldsm4(al[mf], Ab + SWZ((uint32_t)(r * 128 + (chh + 4) * 16)));
            }
#pragma unroll
            for (int nf2 = 0; nf2 < 2; nf2++) {
                int r = wn * 32 + nf2 * 16 + rsub;
                int chh = ks * 2 + csub;
                ldsm4(bh[nf2], Bb + SWZ((uint32_t)(r * 128 + chh * 16)));
                ldsm4(bl[nf2], Bb + SWZ((uint32_t)(r * 128 + (chh + 4) * 16)));
            }
#pragma unroll
            for (int mf = 0; mf < 4; mf++)
#pragma unroll
                for (int nf = 0; nf < 4; nf++) {
                    uint32_t bh0 = bh[nf >> 1][nf & 1], bh1 = bh[nf >> 1][(nf & 1) + 2];
                    uint32_t bl0 = bl[nf >> 1][nf & 1], bl1 = bl[nf >> 1][(nf & 1) + 2];
                    mma16816(acc[mf][nf], ah[mf], bh0, bh1);
                    mma16816(acc[mf][nf], ah[mf], bl0, bl1);
                    mma16816(acc[mf][nf], al[mf], bh0, bh1);
                }
        }
        __syncthreads();
    }

    const int gg = lane >> 2;
    const int tq = lane & 3;
#pragma unroll
    for (int mf = 0; mf < 4; mf++) {
#pragma unroll
        for (int nf = 0; nf < 4; nf++) {
            int row = m0 + wm * 64 + mf * 16 + gg;
            int col = n0 + wn * 32 + nf * 8 + tq * 2;
            *(float2*)(C + (size_t)row * N + col) =
                make_float2(acc[mf][nf][0], acc[mf][nf][1]);
            *(float2*)(C + (size_t)(row + 8) * N + col) =
                make_float2(acc[mf][nf][2], acc[mf][nf][3]);
        }
    }
}

// ---------------------------------------------------------------------------
// RoPE + split into bf16 head-major buffers: q (pre-scaled), k, v hi/lo
// ---------------------------------------------------------------------------
__global__ __launch_bounds__(64) void rope_bf16(
    const float* __restrict__ qkv, const int* __restrict__ positions)
{
    int bidx = blockIdx.x;
    int h  = bidx % NHEADS;
    int ms = bidx / NHEADS;
    int s  = ms % NS;
    int b  = ms / NS;
    int d  = threadIdx.x;

    const float* row = qkv + (size_t)ms * NQKV + h * HDIM;
    const float scale = 0.08838834764831845f;   // 1/sqrt(128)

    double pos = (double)positions[ms];
    double inv = exp(-(double)d * (9.210340371976184 / 64.0));
    double ang = pos * inv;
    double sd, cd;
    sincos(ang, &sd, &cd);
    float sn = (float)sd, cs = (float)cd;

    float q1 = row[d],        q2 = row[d + 64];
    float k1 = row[NHID + d], k2 = row[NHID + d + 64];
    float v1 = row[2 * NHID + d], v2 = row[2 * NHID + d + 64];

    size_t o = ((size_t)((b * NHEADS + h)) * NS + s) * HDIM + d;
    g_qb[o]      = __float2bfloat16_rn((q1 * cs - q2 * sn) * scale);
    g_qb[o + 64] = __float2bfloat16_rn((q2 * cs + q1 * sn) * scale);
    g_kb[o]      = __float2bfloat16_rn(k1 * cs - k2 * sn);
    g_kb[o + 64] = __float2bfloat16_rn(k2 * cs + k1 * sn);

    __nv_bfloat16 vh1 = __float2bfloat16_rn(v1);
    __nv_bfloat16 vh2 = __float2bfloat16_rn(v2);
    g_vhi[o]      = vh1;
    g_vhi[o + 64] = vh2;
    g_vlo[o]      = __float2bfloat16_rn(v1 - __bfloat162float(vh1));
    g_vlo[o + 64] = __float2bfloat16_rn(v2 - __bfloat162float(vh2));
}

// ---------------------------------------------------------------------------
// Flash attention with HMMA. CTA = 128 q-rows, 8 warps (16 rows each),
// k processed in 64-chunks, double-buffered cp.async.
// S = Qbf·Kbf (1 pass); P·V = phi·vhi + phi·vlo + plo·vhi (3 passes).
// smem rows are 256B with per-row XOR-chunk swizzle (conflict-free ldmatrix).
// Epilogue writes hi/lo bf16 split directly into g_ahi/g_alo.
// ---------------------------------------------------------------------------
#define AQT 128
#define AKT 64
#define AKV 16384                        // one 64x256B tile
#define ASTG (3 * AKV)                   // K | Vhi | Vlo
#define ATTN_SMEM (32768 + 2 * ASTG)     // Q + 2 stages = 131072

__global__ __launch_bounds__(256, 1) void attn_mma()
{
    extern __shared__ char smem[];
    const uint32_t sQ = smem_u32(smem);
    const int tid  = threadIdx.x;
    const int lane = tid & 31;
    const int w    = tid >> 5;
    const int qt   = blockIdx.x;
    const int bh   = blockIdx.y;
    const int qs0  = qt * AQT;
    const size_t hb = (size_t)bh * NS * HDIM;

    const int g  = lane >> 2;
    const int t2 = (lane & 3) * 2;
    // ldmatrix per-lane address components (R4-verified pattern)
    const int lr = (lane & 7) + ((lane >> 3) & 1) * 8;
    const int lc = lane >> 4;

    // Q tile: 128 rows x 128 d (bf16), swizzled 256B rows
#pragma unroll
    for (int i = 0; i < 8; i++) {
        int idx = tid + 256 * i;
        int r = idx >> 4, c = idx & 15;
        uint32_t dst = sQ + r * 256 + ((c ^ (r & 7)) << 4);
        cp_async16(dst, g_qb + hb + (size_t)(qs0 + r) * HDIM + c * 8);
    }
    auto load_kv = [&](int kt, int st) {
        int kc0 = kt * AKT;
        uint32_t sb = sQ + 32768 + st * ASTG;
#pragma unroll
        for (int i = 0; i < 12; i++) {
            int idx = tid + 256 * i;             // 0..3071
            int buf = idx >> 10;                 // 0=K 1=Vhi 2=Vlo
            int rem = idx & 1023;
            int r = rem >> 4, c = rem & 15;
            uint32_t dst = sb + buf * AKV + r * 256 + ((c ^ (r & 7)) << 4);
            const __nv_bfloat16* src = buf == 0 ? g_kb : (buf == 1 ? g_vhi : g_vlo);
            cp_async16(dst, src + hb + (size_t)(kc0 + r) * HDIM + c * 8);
        }
    };
    load_kv(0, 0);
    CP_COMMIT();

    float oacc[16][4];
#pragma unroll
    for (int i = 0; i < 16; i++)
#pragma unroll
        for (int v = 0; v < 4; v++) oacc[i][v] = 0.f;
    float m0 = -INFINITY, m1 = -INFINITY, l0 = 0.f, l1 = 0.f;

    const int KN = 2 * qt + 2;
    const int row0 = qs0 + w * 16 + g;

    for (int kt = 0; kt < KN; kt++) {
        if (kt + 1 < KN) {
            load_kv(kt + 1, (kt + 1) & 1);
            CP_COMMIT();
            asm volatile("cp.async.wait_group 1;" ::: "memory");
        } else {
            asm volatile("cp.async.wait_group 0;" ::: "memory");
        }
        __syncthreads();

        // warp tile fully masked? (min col > max row of warp)
        if (kt * AKT <= qs0 + w * 16 + 15) {
            const uint32_t sK  = sQ + 32768 + (kt & 1) * ASTG;
            const uint32_t sVh = sK + AKV;
            const uint32_t sVl = sK + 2 * AKV;

            // ---- S = Q K^T ----
            float sacc[8][4];
#pragma unroll
            for (int nf = 0; nf < 8; nf++)
#pragma unroll
                for (int v = 0; v < 4; v++) sacc[nf][v] = 0.f;

#pragma unroll
            for (int ks = 0; ks < 8; ks++) {
                uint32_t aq[4];
                {
                    int r = w * 16 + lr, c = 2 * ks + lc;
                    ldsm4(aq, sQ + r * 256 + ((c ^ (r & 7)) << 4));
                }
                uint32_t kb4[4][4];
#pragma unroll
                for (int kg = 0; kg < 4; kg++) {
                    int r = kg * 16 + lr, c = 2 * ks + lc;
                    ldsm4(kb4[kg], sK + r * 256 + ((c ^ (r & 7)) << 4));
                }
#pragma unroll
                for (int nf = 0; nf < 8; nf++)
                    mma16816(sacc[nf], aq, kb4[nf >> 1][nf & 1],
                             kb4[nf >> 1][(nf & 1) + 2]);
            }

            // ---- causal mask (diagonal chunks only) ----
            if (kt * AKT + 63 > qs0 + w * 16) {
#pragma unroll
                for (int nf = 0; nf < 8; nf++) {
                    int cb = kt * AKT + nf * 8 + t2;
                    if (cb     > row0)     sacc[nf][0] = -1e30f;
                    if (cb + 1 > row0)     sacc[nf][1] = -1e30f;
                    if (cb     > row0 + 8) sacc[nf][2] = -1e30f;
                    if (cb + 1 > row0 + 8) sacc[nf][3] = -1e30f;
                }
            }

            // ---- online softmax ----
            float mx0 = -1e30f, mx1 = -1e30f;
#pragma unroll
            for (int nf = 0; nf < 8; nf++) {
                mx0 = fmaxf(mx0, fmaxf(sacc[nf][0], sacc[nf][1]));
                mx1 = fmaxf(mx1, fmaxf(sacc[nf][2], sacc[nf][3]));
            }
            mx0 = fmaxf(mx0, __shfl_xor_sync(0xffffffffu, mx0, 1));
            mx0 = fmaxf(mx0, __shfl_xor_sync(0xffffffffu, mx0, 2));
            mx1 = fmaxf(mx1, __shfl_xor_sync(0xffffffffu, mx1, 1));
            mx1 = fmaxf(mx1, __shfl_xor_sync(0xffffffffu, mx1, 2));

            float nm0 = fmaxf(m0, mx0), nm1 = fmaxf(m1, mx1);
            float cr0 = __expf(m0 - nm0), cr1 = __expf(m1 - nm1);
            m0 = nm0; m1 = nm1;
#pragma unroll
            for (int nf = 0; nf < 16; nf++) {
                oacc[nf][0] *= cr0; oacc[nf][1] *= cr0;
                oacc[nf][2] *= cr1; oacc[nf][3] *= cr1;
            }

            float rs0 = 0.f, rs1 = 0.f;
            uint32_t phi[4][4], plo[4][4];
#pragma unroll
            for (int kg = 0; kg < 4; kg++) {
                float p[2][4];
#pragma unroll
                for (int j = 0; j < 2; j++) {
                    int nf = 2 * kg + j;
                    p[j][0] = __expf(sacc[nf][0] - nm0);
                    p[j][1] = __expf(sacc[nf][1] - nm0);
                    p[j][2] = __expf(sacc[nf][2] - nm1);
                    p[j][3] = __expf(sacc[nf][3] - nm1);
                    rs0 += p[j][0] + p[j][1];
                    rs1 += p[j][2] + p[j][3];
                }
                float ph[2][4], pl[2][4];
#pragma unroll
                for (int j = 0; j < 2; j++)
#pragma unroll
                    for (int v = 0; v < 4; v++) {
                        ph[j][v] = __bfloat162float(__float2bfloat16_rn(p[j][v]));
                        pl[j][v] = p[j][v] - ph[j][v];
                    }
                phi[kg][0] = pack_bf16(ph[0][0], ph[0][1]);
                phi[kg][1] = pack_bf16(ph[0][2], ph[0][3]);
                phi[kg][2] = pack_bf16(ph[1][0], ph[1][1]);
                phi[kg][3] = pack_bf16(ph[1][2], ph[1][3]);
                plo[kg][0] = pack_bf16(pl[0][0], pl[0][1]);
                plo[kg][1] = pack_bf16(pl[0][2], pl[0][3]);
                plo[kg][2] = pack_bf16(pl[1][0], pl[1][1]);
                plo[kg][3] = pack_bf16(pl[1][2], pl[1][3]);
            }
            rs0 += __shfl_xor_sync(0xffffffffu, rs0, 1);
            rs0 += __shfl_xor_sync(0xffffffffu, rs0, 2);
            rs1 += __shfl_xor_sync(0xffffffffu, rs1, 1);
            rs1 += __shfl_xor_sync(0xffffffffu, rs1, 2);
            l0 = l0 * cr0 + rs0;
            l1 = l1 * cr1 + rs1;

            // ---- O += P V  (3-pass hi/lo) ----
#pragma unroll
            for (int dg = 0; dg < 8; dg++) {
#pragma unroll
                for (int kg = 0; kg < 4; kg++) {
                    int r = kg * 16 + lr, c = 2 * dg + lc;
                    uint32_t off = (uint32_t)(r * 256 + ((c ^ (r & 7)) << 4));
                    uint32_t vh[4], vl[4];
                    ldsm4t(vh, sVh + off);
                    ldsm4t(vl, sVl + off);
                    mma16816(oacc[2 * dg],     phi[kg], vh[0], vh[1]);
                    mma16816(oacc[2 * dg],     phi[kg], vl[0], vl[1]);
                    mma16816(oacc[2 * dg],     plo[kg], vh[0], vh[1]);
                    mma16816(oacc[2 * dg + 1], phi[kg], vh[2], vh[3]);
                    mma16816(oacc[2 * dg + 1], phi[kg], vl[2], vl[3]);
                    mma16816(oacc[2 * dg + 1], plo[kg], vh[2], vh[3]);
                }
            }
        }
        __syncthreads();
    }

    // ---- epilogue: normalize, hi/lo split, write to GEMM-A buffers ----
    float inv0 = 1.f / l0, inv1 = 1.f / l1;
    const int b = bh >> 5, h = bh & 31;
    size_t ob0 = (size_t)(b * NS + row0) * NHID + h * HDIM + t2;
    size_t ob1 = ob0 + (size_t)8 * NHID;
#pragma unroll
    for (int nf = 0; nf < 16; nf++) {
        float x0 = oacc[nf][0] * inv0, y0 = oacc[nf][1] * inv0;
        float x1 = oacc[nf][2] * inv1, y1 = oacc[nf][3] * inv1;
        float hx0 = __bfloat162float(__float2bfloat16_rn(x0));
        float hy0 = __bfloat162float(__float2bfloat16_rn(y0));
        float hx1 = __bfloat162float(__float2bfloat16_rn(x1));
        float hy1 = __bfloat162float(__float2bfloat16_rn(y1));
        *(uint32_t*)(g_ahi + ob0 + nf * 8) = pack_bf16(hx0, hy0);
        *(uint32_t*)(g_alo + ob0 + nf * 8) = pack_bf16(x0 - hx0, y0 - hy0);
        *(uint32_t*)(g_ahi + ob1 + nf * 8) = pack_bf16(hx1, hy1);
        *(uint32_t*)(g_alo + ob1 + nf * 8) = pack_bf16(x1 - hx1, y1 - hy1);
    }
}

// ---------------------------------------------------------------------------
// Launch
// ---------------------------------------------------------------------------
extern "C" void kernel_launch(void* const* d_in, const int* in_sizes, int n_in,
                              void* d_out, int out_size)
{
    const float* hs  = (const float*)d_in[0];   // [B,S,H]
    const int*   pos = (const int*)  d_in[1];   // [B,S]
    const float* wp  = (const float*)d_in[2];   // [3H,H]
    const float* wo  = (const float*)d_in[3];   // [H,H]
    float* out = (float*)d_out;                 // [B,S,H]

    float* qkv; cudaGetSymbolAddress((void**)&qkv, g_qkv);
    __nv_bfloat16 *ahi, *alo, *bhi, *blo;
    cudaGetSymbolAddress((void**)&ahi, g_ahi);
    cudaGetSymbolAddress((void**)&alo, g_alo);
    cudaGetSymbolAddress((void**)&bhi, g_bhi);
    cudaGetSymbolAddress((void**)&blo, g_blo);

    cudaFuncSetAttribute(gemm_bf16, cudaFuncAttributeMaxDynamicSharedMemorySize, GEMM_SMEM);
    cudaFuncSetAttribute(attn_mma, cudaFuncAttributeMaxDynamicSharedMemorySize, ATTN_SMEM);

    // 1. split inputs to bf16 hi/lo
    split_bf16<<<(size_t)MTOK * NHID / 1024, 256>>>(hs, ahi, alo);
    split_bf16<<<(size_t)NQKV * NHID / 1024, 256>>>(wp, bhi, blo);

    // 2. QKV projection (tensor cores)
    gemm_bf16<<<dim3(MTOK / 128, NQKV / 128), 256, GEMM_SMEM>>>(
        ahi, alo, bhi, blo, qkv, MTOK, NQKV, NHID);

    // 3. RoPE + bf16 head-major split (q pre-scaled, v hi/lo)
    rope_bf16<<<NB * NS * NHEADS, 64>>>(qkv, pos);

    // 4. Causal flash attention (HMMA); writes hi/lo split output
    attn_mma<<<dim3(NS / AQT, NB * NHEADS), 256, ATTN_SMEM>>>();

    // 5. output projection
    split_bf16<<<(size_t)NHID * NHID / 1024, 256>>>(wo, bhi, blo);
    gemm_bf16<<<dim3(MTOK / 128, NHID / 128), 256, GEMM_SMEM>>>(
        ahi, alo, bhi, blo, out, MTOK, NHID, NHID);
}

// round 6
// speedup vs baseline: 7.0865x; 2.6620x over previous
#include <cuda_runtime.h>
#include <cuda_bf16.h>
#include <cuda_fp16.h>
#include <math.h>
#include <stdint.h>

// Problem constants
#define NB 2
#define NS 2048
#define NHID 4096
#define NHEADS 32
#define HDIM 128
#define NQKV 12288   // 3*NHID
#define MTOK 4096    // NB*NS

// Scratch (device globals: allocation-free per harness rules)
__device__ float g_qkv[(size_t)MTOK * NQKV];               // 201 MB
__device__ __nv_bfloat16 g_qb [(size_t)NB * NHEADS * NS * HDIM];  // bf16, q*scale
__device__ __nv_bfloat16 g_kb [(size_t)NB * NHEADS * NS * HDIM];
__device__ __nv_bfloat16 g_vhi[(size_t)NB * NHEADS * NS * HDIM];
__device__ __nv_bfloat16 g_vlo[(size_t)NB * NHEADS * NS * HDIM];
__device__ __half g_a16[(size_t)MTOK * NHID];              // GEMM A (fp16)
__device__ __half g_b16[(size_t)NQKV * NHID];              // GEMM B (fp16)

// ---------------------------------------------------------------------------
// Helpers (baseline PTX, valid on compute_100)
// ---------------------------------------------------------------------------
__device__ __forceinline__ uint32_t smem_u32(const void* p) {
    uint32_t a;
    asm("{ .reg .u64 t; cvta.to.shared.u64 t, %1; cvt.u32.u64 %0, t; }"
        : "=r"(a) : "l"(p));
    return a;
}

__device__ __forceinline__ void cp_async16(uint32_t dst, const void* src) {
    asm volatile("cp.async.cg.shared.global [%0], [%1], 16;" :: "r"(dst), "l"(src));
}
#define CP_COMMIT() asm volatile("cp.async.commit_group;" ::: "memory")

__device__ __forceinline__ void ldsm4(uint32_t* r, uint32_t addr) {
    asm volatile("ldmatrix.sync.aligned.m8n8.x4.shared.b16 {%0,%1,%2,%3}, [%4];"
                 : "=r"(r[0]), "=r"(r[1]), "=r"(r[2]), "=r"(r[3]) : "r"(addr));
}
__device__ __forceinline__ void ldsm4t(uint32_t* r, uint32_t addr) {
    asm volatile("ldmatrix.sync.aligned.m8n8.x4.trans.shared.b16 {%0,%1,%2,%3}, [%4];"
                 : "=r"(r[0]), "=r"(r[1]), "=r"(r[2]), "=r"(r[3]) : "r"(addr));
}

__device__ __forceinline__ void mma16816(float* c, const uint32_t* a,
                                         uint32_t b0, uint32_t b1) {   // bf16
    asm volatile(
        "mma.sync.aligned.m16n8k16.row.col.f32.bf16.bf16.f32 "
        "{%0,%1,%2,%3}, {%4,%5,%6,%7}, {%8,%9}, {%0,%1,%2,%3};"
        : "+f"(c[0]), "+f"(c[1]), "+f"(c[2]), "+f"(c[3])
        : "r"(a[0]), "r"(a[1]), "r"(a[2]), "r"(a[3]), "r"(b0), "r"(b1));
}
__device__ __forceinline__ void mma16816h(float* c, const uint32_t* a,
                                          uint32_t b0, uint32_t b1) {  // fp16
    asm volatile(
        "mma.sync.aligned.m16n8k16.row.col.f32.f16.f16.f32 "
        "{%0,%1,%2,%3}, {%4,%5,%6,%7}, {%8,%9}, {%0,%1,%2,%3};"
        : "+f"(c[0]), "+f"(c[1]), "+f"(c[2]), "+f"(c[3])
        : "r"(a[0]), "r"(a[1]), "r"(a[2]), "r"(a[3]), "r"(b0), "r"(b1));
}

#define SWZ(x) ((x) ^ (((x) >> 3) & 0x70))

__device__ __forceinline__ uint32_t pack_bf16(float x, float y) {
    __nv_bfloat162 t(__float2bfloat16_rn(x), __float2bfloat16_rn(y));
    return *(uint32_t*)&t;
}
__device__ __forceinline__ uint32_t pack_f16(float x, float y) {
    __half2 t = __floats2half2_rn(x, y);
    return *(uint32_t*)&t;
}

// ---------------------------------------------------------------------------
// convert: fp32 -> fp16
// ---------------------------------------------------------------------------
__global__ __launch_bounds__(256) void conv_f16(
    const float* __restrict__ x, __half* __restrict__ o)
{
    size_t i = ((size_t)blockIdx.x * 256 + threadIdx.x) * 4;
    float4 v = *(const float4*)(x + i);
    uint2 r;
    r.x = pack_f16(v.x, v.y);
    r.y = pack_f16(v.z, v.w);
    *(uint2*)(o + i) = r;
}

// ---------------------------------------------------------------------------
// fp16 single-pass GEMM (NT): C[m,n] = sum_k A[m,k]*B[n,k]
// CTA 128x128, 8 warps (2m x 4n), KTILE=64, double-buffered cp.async,
// 2 CTAs/SM. smem row = 128B (64 fp16) with SW128 swizzle.
// ---------------------------------------------------------------------------
#define FKT 64
#define FBUF 16384                  // 128 rows x 128 B
#define FSTG (2 * FBUF)             // A + B
#define GEMM_SMEM (2 * FSTG)        // double buffer: 64 KB

__global__ __launch_bounds__(256, 2) void gemm_f16(
    const __half* __restrict__ A, const __half* __restrict__ B,
    float* __restrict__ C, int M, int N, int K)
{
    extern __shared__ char smem[];
    const uint32_t sbase = smem_u32(smem);

    const int tid  = threadIdx.x;
    const int lane = tid & 31;
    const int wid  = tid >> 5;
    const int wm   = wid >> 2;
    const int wn   = wid & 3;
    const int m0   = blockIdx.x * 128;
    const int n0   = blockIdx.y * 128;

    auto load_stage = [&](int kt, int st) {
        const int kk = kt * FKT;
        const uint32_t su = sbase + st * FSTG;
#pragma unroll
        for (int i = 0; i < 8; i++) {
            int c   = tid + 256 * i;        // 0..2047
            int op  = c >> 10;              // 0=A, 1=B
            int rem = c & 1023;
            int r   = rem >> 3;             // row 0..127
            int ch  = rem & 7;              // 16B chunk 0..7
            uint32_t dst = su + op * FBUF + SWZ((uint32_t)(r * 128 + ch * 16));
            const __half* src = op ? B : A;
            size_t gaddr = (size_t)((op ? n0 : m0) + r) * K + kk + ch * 8;
            cp_async16(dst, src + gaddr);
        }
        CP_COMMIT();
    };

    float acc[4][4][4];
#pragma unroll
    for (int i = 0; i < 4; i++)
#pragma unroll
        for (int j = 0; j < 4; j++)
#pragma unroll
            for (int v = 0; v < 4; v++) acc[i][j][v] = 0.f;

    const int KT = K / FKT;
    load_stage(0, 0);

    const int mat  = lane >> 3;
    const int rsub = (mat & 1) * 8 + (lane & 7);
    const int csub = mat >> 1;

    for (int kt = 0; kt < KT; kt++) {
        if (kt + 1 < KT) {
            load_stage(kt + 1, (kt + 1) & 1);
            asm volatile("cp.async.wait_group 1;" ::: "memory");
        } else {
            asm volatile("cp.async.wait_group 0;" ::: "memory");
        }
        __syncthreads();

        const uint32_t Ab = sbase + (kt & 1) * FSTG;
        const uint32_t Bb = Ab + FBUF;

#pragma unroll
        for (int ks = 0; ks < 4; ks++) {
            uint32_t af[4][4], bf[2][4];
            const int chh = ks * 2 + csub;
#pragma unroll
            for (int mf = 0; mf < 4; mf++) {
                int r = wm * 64 + mf * 16 + rsub;
                ldsm4(af[mf], Ab + SWZ((uint32_t)(r * 128 + chh * 16)));
            }
#pragma unroll
            for (int nf2 = 0; nf2 < 2; nf2++) {
                int r = wn * 32 + nf2 * 16 + rsub;
                ldsm4(bf[nf2], Bb + SWZ((uint32_t)(r * 128 + chh * 16)));
            }
#pragma unroll
            for (int mf = 0; mf < 4; mf++)
#pragma unroll
                for (int nf = 0; nf < 4; nf++)
                    mma16816h(acc[mf][nf], af[mf],
                              bf[nf >> 1][nf & 1], bf[nf >> 1][(nf & 1) + 2]);
        }
        __syncthreads();
    }

    const int gg = lane >> 2;
    const int tq = lane & 3;
#pragma unroll
    for (int mf = 0; mf < 4; mf++) {
#pragma unroll
        for (int nf = 0; nf < 4; nf++) {
            int row = m0 + wm * 64 + mf * 16 + gg;
            int col = n0 + wn * 32 + nf * 8 + tq * 2;
            *(float2*)(C + (size_t)row * N + col) =
                make_float2(acc[mf][nf][0], acc[mf][nf][1]);
            *(float2*)(C + (size_t)(row + 8) * N + col) =
                make_float2(acc[mf][nf][2], acc[mf][nf][3]);
        }
    }
}

// ---------------------------------------------------------------------------
// RoPE + split into bf16 head-major buffers: q (pre-scaled), k, v hi/lo
// ---------------------------------------------------------------------------
__global__ __launch_bounds__(64) void rope_bf16(
    const float* __restrict__ qkv, const int* __restrict__ positions)
{
    int bidx = blockIdx.x;
    int h  = bidx % NHEADS;
    int ms = bidx / NHEADS;
    int s  = ms % NS;
    int b  = ms / NS;
    int d  = threadIdx.x;

    const float* row = qkv + (size_t)ms * NQKV + h * HDIM;
    const float scale = 0.08838834764831845f;   // 1/sqrt(128)

    double pos = (double)positions[ms];
    double inv = exp(-(double)d * (9.210340371976184 / 64.0));
    double ang = pos * inv;
    double sd, cd;
    sincos(ang, &sd, &cd);
    float sn = (float)sd, cs = (float)cd;

    float q1 = row[d],        q2 = row[d + 64];
    float k1 = row[NHID + d], k2 = row[NHID + d + 64];
    float v1 = row[2 * NHID + d], v2 = row[2 * NHID + d + 64];

    size_t o = ((size_t)((b * NHEADS + h)) * NS + s) * HDIM + d;
    g_qb[o]      = __float2bfloat16_rn((q1 * cs - q2 * sn) * scale);
    g_qb[o + 64] = __float2bfloat16_rn((q2 * cs + q1 * sn) * scale);
    g_kb[o]      = __float2bfloat16_rn(k1 * cs - k2 * sn);
    g_kb[o + 64] = __float2bfloat16_rn(k2 * cs + k1 * sn);

    __nv_bfloat16 vh1 = __float2bfloat16_rn(v1);
    __nv_bfloat16 vh2 = __float2bfloat16_rn(v2);
    g_vhi[o]      = vh1;
    g_vhi[o + 64] = vh2;
    g_vlo[o]      = __float2bfloat16_rn(v1 - __bfloat162float(vh1));
    g_vlo[o + 64] = __float2bfloat16_rn(v2 - __bfloat162float(vh2));
}

// ---------------------------------------------------------------------------
// Flash attention with HMMA (unchanged math from R5; epilogue now fp16)
// ---------------------------------------------------------------------------
#define AQT 128
#define AKT 64
#define AKV 16384
#define ASTG (3 * AKV)
#define ATTN_SMEM (32768 + 2 * ASTG)

__global__ __launch_bounds__(256, 1) void attn_mma()
{
    extern __shared__ char smem[];
    const uint32_t sQ = smem_u32(smem);
    const int tid  = threadIdx.x;
    const int lane = tid & 31;
    const int w    = tid >> 5;
    const int qt   = blockIdx.x;
    const int bh   = blockIdx.y;
    const int qs0  = qt * AQT;
    const size_t hb = (size_t)bh * NS * HDIM;

    const int g  = lane >> 2;
    const int t2 = (lane & 3) * 2;
    const int lr = (lane & 7) + ((lane >> 3) & 1) * 8;
    const int lc = lane >> 4;

#pragma unroll
    for (int i = 0; i < 8; i++) {
        int idx = tid + 256 * i;
        int r = idx >> 4, c = idx & 15;
        uint32_t dst = sQ + r * 256 + ((c ^ (r & 7)) << 4);
        cp_async16(dst, g_qb + hb + (size_t)(qs0 + r) * HDIM + c * 8);
    }
    auto load_kv = [&](int kt, int st) {
        int kc0 = kt * AKT;
        uint32_t sb = sQ + 32768 + st * ASTG;
#pragma unroll
        for (int i = 0; i < 12; i++) {
            int idx = tid + 256 * i;
            int buf = idx >> 10;
            int rem = idx & 1023;
            int r = rem >> 4, c = rem & 15;
            uint32_t dst = sb + buf * AKV + r * 256 + ((c ^ (r & 7)) << 4);
            const __nv_bfloat16* src = buf == 0 ? g_kb : (buf == 1 ? g_vhi : g_vlo);
            cp_async16(dst, src + hb + (size_t)(kc0 + r) * HDIM + c * 8);
        }
    };
    load_kv(0, 0);
    CP_COMMIT();

    float oacc[16][4];
#pragma unroll
    for (int i = 0; i < 16; i++)
#pragma unroll
        for (int v = 0; v < 4; v++) oacc[i][v] = 0.f;
    float m0 = -INFINITY, m1 = -INFINITY, l0 = 0.f, l1 = 0.f;

    const int KN = 2 * qt + 2;
    const int row0 = qs0 + w * 16 + g;

    for (int kt = 0; kt < KN; kt++) {
        if (kt + 1 < KN) {
            load_kv(kt + 1, (kt + 1) & 1);
            CP_COMMIT();
            asm volatile("cp.async.wait_group 1;" ::: "memory");
        } else {
            asm volatile("cp.async.wait_group 0;" ::: "memory");
        }
        __syncthreads();

        if (kt * AKT <= qs0 + w * 16 + 15) {
            const uint32_t sK  = sQ + 32768 + (kt & 1) * ASTG;
            const uint32_t sVh = sK + AKV;
            const uint32_t sVl = sK + 2 * AKV;

            float sacc[8][4];
#pragma unroll
            for (int nf = 0; nf < 8; nf++)
#pragma unroll
                for (int v = 0; v < 4; v++) sacc[nf][v] = 0.f;

#pragma unroll
            for (int ks = 0; ks < 8; ks++) {
                uint32_t aq[4];
                {
                    int r = w * 16 + lr, c = 2 * ks + lc;
                    ldsm4(aq, sQ + r * 256 + ((c ^ (r & 7)) << 4));
                }
                uint32_t kb4[4][4];
#pragma unroll
                for (int kg = 0; kg < 4; kg++) {
                    int r = kg * 16 + lr, c = 2 * ks + lc;
                    ldsm4(kb4[kg], sK + r * 256 + ((c ^ (r & 7)) << 4));
                }
#pragma unroll
                for (int nf = 0; nf < 8; nf++)
                    mma16816(sacc[nf], aq, kb4[nf >> 1][nf & 1],
                             kb4[nf >> 1][(nf & 1) + 2]);
            }

            if (kt * AKT + 63 > qs0 + w * 16) {
#pragma unroll
                for (int nf = 0; nf < 8; nf++) {
                    int cb = kt * AKT + nf * 8 + t2;
                    if (cb     > row0)     sacc[nf][0] = -1e30f;
                    if (cb + 1 > row0)     sacc[nf][1] = -1e30f;
                    if (cb     > row0 + 8) sacc[nf][2] = -1e30f;
                    if (cb + 1 > row0 + 8) sacc[nf][3] = -1e30f;
                }
            }

            float mx0 = -1e30f, mx1 = -1e30f;
#pragma unroll
            for (int nf = 0; nf < 8; nf++) {
                mx0 = fmaxf(mx0, fmaxf(sacc[nf][0], sacc[nf][1]));
                mx1 = fmaxf(mx1, fmaxf(sacc[nf][2], sacc[nf][3]));
            }
            mx0 = fmaxf(mx0, __shfl_xor_sync(0xffffffffu, mx0, 1));
            mx0 = fmaxf(mx0, __shfl_xor_sync(0xffffffffu, mx0, 2));
            mx1 = fmaxf(mx1, __shfl_xor_sync(0xffffffffu, mx1, 1));
            mx1 = fmaxf(mx1, __shfl_xor_sync(0xffffffffu, mx1, 2));

            float nm0 = fmaxf(m0, mx0), nm1 = fmaxf(m1, mx1);
            float cr0 = __expf(m0 - nm0), cr1 = __expf(m1 - nm1);
            m0 = nm0; m1 = nm1;
#pragma unroll
            for (int nf = 0; nf < 16; nf++) {
                oacc[nf][0] *= cr0; oacc[nf][1] *= cr0;
                oacc[nf][2] *= cr1; oacc[nf][3] *= cr1;
            }

            float rs0 = 0.f, rs1 = 0.f;
            uint32_t phi[4][4], plo[4][4];
#pragma unroll
            for (int kg = 0; kg < 4; kg++) {
                float p[2][4];
#pragma unroll
                for (int j = 0; j < 2; j++) {
                    int nf = 2 * kg + j;
                    p[j][0] = __expf(sacc[nf][0] - nm0);
                    p[j][1] = __expf(sacc[nf][1] - nm0);
                    p[j][2] = __expf(sacc[nf][2] - nm1);
                    p[j][3] = __expf(sacc[nf][3] - nm1);
                    rs0 += p[j][0] + p[j][1];
                    rs1 += p[j][2] + p[j][3];
                }
                float ph[2][4], pl[2][4];
#pragma unroll
                for (int j = 0; j < 2; j++)
#pragma unroll
                    for (int v = 0; v < 4; v++) {
                        ph[j][v] = __bfloat162float(__float2bfloat16_rn(p[j][v]));
                        pl[j][v] = p[j][v] - ph[j][v];
                    }
                phi[kg][0] = pack_bf16(ph[0][0], ph[0][1]);
                phi[kg][1] = pack_bf16(ph[0][2], ph[0][3]);
                phi[kg][2] = pack_bf16(ph[1][0], ph[1][1]);
                phi[kg][3] = pack_bf16(ph[1][2], ph[1][3]);
                plo[kg][0] = pack_bf16(pl[0][0], pl[0][1]);
                plo[kg][1] = pack_bf16(pl[0][2], pl[0][3]);
                plo[kg][2] = pack_bf16(pl[1][0], pl[1][1]);
                plo[kg][3] = pack_bf16(pl[1][2], pl[1][3]);
            }
            rs0 += __shfl_xor_sync(0xffffffffu, rs0, 1);
            rs0 += __shfl_xor_sync(0xffffffffu, rs0, 2);
            rs1 += __shfl_xor_sync(0xffffffffu, rs1, 1);
            rs1 += __shfl_xor_sync(0xffffffffu, rs1, 2);
            l0 = l0 * cr0 + rs0;
            l1 = l1 * cr1 + rs1;

#pragma unroll
            for (int dg = 0; dg < 8; dg++) {
#pragma unroll
                for (int kg = 0; kg < 4; kg++) {
                    int r = kg * 16 + lr, c = 2 * dg + lc;
                    uint32_t off = (uint32_t)(r * 256 + ((c ^ (r & 7)) << 4));
                    uint32_t vh[4], vl[4];
                    ldsm4t(vh, sVh + off);
                    ldsm4t(vl, sVl + off);
                    mma16816(oacc[2 * dg],     phi[kg], vh[0], vh[1]);
                    mma16816(oacc[2 * dg],     phi[kg], vl[0], vl[1]);
                    mma16816(oacc[2 * dg],     plo[kg], vh[0], vh[1]);
                    mma16816(oacc[2 * dg + 1], phi[kg], vh[2], vh[3]);
                    mma16816(oacc[2 * dg + 1], phi[kg], vl[2], vl[3]);
                    mma16816(oacc[2 * dg + 1], plo[kg], vh[2], vh[3]);
                }
            }
        }
        __syncthreads();
    }

    // epilogue: normalize, write fp16 into out-proj A buffer
    float inv0 = 1.f / l0, inv1 = 1.f / l1;
    const int b = bh >> 5, h = bh & 31;
    size_t ob0 = (size_t)(b * NS + row0) * NHID + h * HDIM + t2;
    size_t ob1 = ob0 + (size_t)8 * NHID;
#pragma unroll
    for (int nf = 0; nf < 16; nf++) {
        *(uint32_t*)(g_a16 + ob0 + nf * 8) =
            pack_f16(oacc[nf][0] * inv0, oacc[nf][1] * inv0);
        *(uint32_t*)(g_a16 + ob1 + nf * 8) =
            pack_f16(oacc[nf][2] * inv1, oacc[nf][3] * inv1);
    }
}

// ---------------------------------------------------------------------------
// Launch
// ---------------------------------------------------------------------------
extern "C" void kernel_launch(void* const* d_in, const int* in_sizes, int n_in,
                              void* d_out, int out_size)
{
    const float* hs  = (const float*)d_in[0];   // [B,S,H]
    const int*   pos = (const int*)  d_in[1];   // [B,S]
    const float* wp  = (const float*)d_in[2];   // [3H,H]
    const float* wo  = (const float*)d_in[3];   // [H,H]
    float* out = (float*)d_out;                 // [B,S,H]

    float* qkv; cudaGetSymbolAddress((void**)&qkv, g_qkv);
    __half *a16, *b16;
    cudaGetSymbolAddress((void**)&a16, g_a16);
    cudaGetSymbolAddress((void**)&b16, g_b16);

    cudaFuncSetAttribute(gemm_f16, cudaFuncAttributeMaxDynamicSharedMemorySize, GEMM_SMEM);
    cudaFuncSetAttribute(attn_mma, cudaFuncAttributeMaxDynamicSharedMemorySize, ATTN_SMEM);

    // 1. convert inputs to fp16
    conv_f16<<<(size_t)MTOK * NHID / 1024, 256>>>(hs, a16);
    conv_f16<<<(size_t)NQKV * NHID / 1024, 256>>>(wp, b16);

    // 2. QKV projection (fp16 tensor cores, single pass)
    gemm_f16<<<dim3(MTOK / 128, NQKV / 128), 256, GEMM_SMEM>>>(
        a16, b16, qkv, MTOK, NQKV, NHID);

    // 3. RoPE + bf16 head-major split
    rope_bf16<<<NB * NS * NHEADS, 64>>>(qkv, pos);

    // 4. Causal flash attention (bf16 HMMA, 3-pass PV); fp16 output
    attn_mma<<<dim3(NS / AQT, NB * NHEADS), 256, ATTN_SMEM>>>();

    // 5. output projection
    conv_f16<<<(size_t)NHID * NHID / 1024, 256>>>(wo, b16);
    gemm_f16<<<dim3(MTOK / 128, NHID / 128), 256, GEMM_SMEM>>>(
        a16, b16, out, MTOK, NHID, NHID);
}

// round 9
// speedup vs baseline: 7.7369x; 1.0918x over previous
#include <cuda_runtime.h>
#include <cuda_bf16.h>
#include <cuda_fp16.h>
#include <math.h>
#include <stdint.h>

// Problem constants
#define NB 2
#define NS 2048
#define NHID 4096
#define NHEADS 32
#define HDIM 128
#define NQKV 12288   // 3*NHID
#define MTOK 4096    // NB*NS

// Scratch (device globals: allocation-free per harness rules)
__device__ __half g_qkv[(size_t)MTOK * NQKV];              // 100 MB (fp16)
__device__ __half g_q16[(size_t)NB * NHEADS * NS * HDIM];  // head-major, q*scale
__device__ __half g_k16[(size_t)NB * NHEADS * NS * HDIM];
__device__ __half g_v16[(size_t)NB * NHEADS * NS * HDIM];
__device__ __half g_a16[(size_t)MTOK * NHID];              // GEMM A (fp16)
__device__ __half g_b16[(size_t)NQKV * NHID];              // GEMM B (fp16)

// ---------------------------------------------------------------------------
// Helpers (baseline PTX, valid on compute_100)
// ---------------------------------------------------------------------------
__device__ __forceinline__ uint32_t smem_u32(const void* p) {
    uint32_t a;
    asm("{ .reg .u64 t; cvta.to.shared.u64 t, %1; cvt.u32.u64 %0, t; }"
        : "=r"(a) : "l"(p));
    return a;
}

__device__ __forceinline__ void cp_async16(uint32_t dst, const void* src) {
    asm volatile("cp.async.cg.shared.global [%0], [%1], 16;" :: "r"(dst), "l"(src));
}
#define CP_COMMIT() asm volatile("cp.async.commit_group;" ::: "memory")

__device__ __forceinline__ void ldsm4(uint32_t* r, uint32_t addr) {
    asm volatile("ldmatrix.sync.aligned.m8n8.x4.shared.b16 {%0,%1,%2,%3}, [%4];"
                 : "=r"(r[0]), "=r"(r[1]), "=r"(r[2]), "=r"(r[3]) : "r"(addr));
}
__device__ __forceinline__ void ldsm4t(uint32_t* r, uint32_t addr) {
    asm volatile("ldmatrix.sync.aligned.m8n8.x4.trans.shared.b16 {%0,%1,%2,%3}, [%4];"
                 : "=r"(r[0]), "=r"(r[1]), "=r"(r[2]), "=r"(r[3]) : "r"(addr));
}

__device__ __forceinline__ void mma16816h(float* c, const uint32_t* a,
                                          uint32_t b0, uint32_t b1) {  // fp16
    asm volatile(
        "mma.sync.aligned.m16n8k16.row.col.f32.f16.f16.f32 "
        "{%0,%1,%2,%3}, {%4,%5,%6,%7}, {%8,%9}, {%0,%1,%2,%3};"
        : "+f"(c[0]), "+f"(c[1]), "+f"(c[2]), "+f"(c[3])
        : "r"(a[0]), "r"(a[1]), "r"(a[2]), "r"(a[3]), "r"(b0), "r"(b1));
}

#define SWZ(x) ((x) ^ (((x) >> 3) & 0x70))

__device__ __forceinline__ uint32_t pack_f16(float x, float y) {
    __half2 t = __floats2half2_rn(x, y);
    return *(uint32_t*)&t;
}

// ---------------------------------------------------------------------------
// convert: fp32 -> fp16
// ---------------------------------------------------------------------------
__global__ __launch_bounds__(256) void conv_f16(
    const float* __restrict__ x, __half* __restrict__ o)
{
    size_t i = ((size_t)blockIdx.x * 256 + threadIdx.x) * 4;
    float4 v = *(const float4*)(x + i);
    uint2 r;
    r.x = pack_f16(v.x, v.y);
    r.y = pack_f16(v.z, v.w);
    *(uint2*)(o + i) = r;
}

// ---------------------------------------------------------------------------
// fp16 single-pass GEMM (NT): C[m,n] = sum_k A[m,k]*B[n,k]
// CTA 128x128, 8 warps (2m x 4n), KTILE=64, 3-stage cp.async, 2 CTAs/SM.
// Output type templated (fp16 for QKV, fp32 for final projection).
// ---------------------------------------------------------------------------
#define FKT 64
#define FBUF 16384                  // 128 rows x 128 B
#define FSTG (2 * FBUF)             // A + B per stage
#define GEMM_SMEM (3 * FSTG)        // 3 stages: 96 KB

template <typename OutT>
__global__ __launch_bounds__(256, 2) void gemm_f16(
    const __half* __restrict__ A, const __half* __restrict__ B,
    OutT* __restrict__ C, int M, int N, int K)
{
    extern __shared__ char smem[];
    const uint32_t sbase = smem_u32(smem);

    const int tid  = threadIdx.x;
    const int lane = tid & 31;
    const int wid  = tid >> 5;
    const int wm   = wid >> 2;
    const int wn   = wid & 3;
    const int m0   = blockIdx.x * 128;
    const int n0   = blockIdx.y * 128;

    auto load_stage = [&](int kt) {
        const int kk = kt * FKT;
        const uint32_t su = sbase + (kt % 3) * FSTG;
#pragma unroll
        for (int i = 0; i < 8; i++) {
            int c   = tid + 256 * i;        // 0..2047
            int op  = c >> 10;              // 0=A, 1=B
            int rem = c & 1023;
            int r   = rem >> 3;             // row 0..127
            int ch  = rem & 7;              // 16B chunk 0..7
            uint32_t dst = su + op * FBUF + SWZ((uint32_t)(r * 128 + ch * 16));
            const __half* src = op ? B : A;
            size_t gaddr = (size_t)((op ? n0 : m0) + r) * K + kk + ch * 8;
            cp_async16(dst, src + gaddr);
        }
        CP_COMMIT();
    };

    float acc[4][4][4];
#pragma unroll
    for (int i = 0; i < 4; i++)
#pragma unroll
        for (int j = 0; j < 4; j++)
#pragma unroll
            for (int v = 0; v < 4; v++) acc[i][j][v] = 0.f;

    const int KT = K / FKT;
    load_stage(0);
    load_stage(1);

    const int mat  = lane >> 3;
    const int rsub = (mat & 1) * 8 + (lane & 7);
    const int csub = mat >> 1;

    for (int kt = 0; kt < KT; kt++) {
        // ensure group kt is complete: with loads issued through kt+1 there may
        // be 2 groups pending; on the LAST iteration only group kt remains, so
        // wait_group must drain to 0 (race otherwise).
        if (kt + 1 < KT) {
            asm volatile("cp.async.wait_group 1;" ::: "memory");
        } else {
            asm volatile("cp.async.wait_group 0;" ::: "memory");
        }
        __syncthreads();
        if (kt + 2 < KT) load_stage(kt + 2);

        const uint32_t Ab = sbase + (kt % 3) * FSTG;
        const uint32_t Bb = Ab + FBUF;

#pragma unroll
        for (int ks = 0; ks < 4; ks++) {
            uint32_t af[4][4], bf[2][4];
            const int chh = ks * 2 + csub;
#pragma unroll
            for (int mf = 0; mf < 4; mf++) {
                int r = wm * 64 + mf * 16 + rsub;
                ldsm4(af[mf], Ab + SWZ((uint32_t)(r * 128 + chh * 16)));
            }
#pragma unroll
            for (int nf2 = 0; nf2 < 2; nf2++) {
                int r = wn * 32 + nf2 * 16 + rsub;
                ldsm4(bf[nf2], Bb + SWZ((uint32_t)(r * 128 + chh * 16)));
            }
#pragma unroll
            for (int mf = 0; mf < 4; mf++)
#pragma unroll
                for (int nf = 0; nf < 4; nf++)
                    mma16816h(acc[mf][nf], af[mf],
                              bf[nf >> 1][nf & 1], bf[nf >> 1][(nf & 1) + 2]);
        }
        __syncthreads();
    }

    const int gg = lane >> 2;
    const int tq = lane & 3;
#pragma unroll
    for (int mf = 0; mf < 4; mf++) {
#pragma unroll
        for (int nf = 0; nf < 4; nf++) {
            int row = m0 + wm * 64 + mf * 16 + gg;
            int col = n0 + wn * 32 + nf * 8 + tq * 2;
            if (sizeof(OutT) == 4) {
                *(float2*)((float*)C + (size_t)row * N + col) =
                    make_float2(acc[mf][nf][0], acc[mf][nf][1]);
                *(float2*)((float*)C + (size_t)(row + 8) * N + col) =
                    make_float2(acc[mf][nf][2], acc[mf][nf][3]);
            } else {
                *(uint32_t*)((__half*)C + (size_t)row * N + col) =
                    pack_f16(acc[mf][nf][0], acc[mf][nf][1]);
                *(uint32_t*)((__half*)C + (size_t)(row + 8) * N + col) =
                    pack_f16(acc[mf][nf][2], acc[mf][nf][3]);
            }
        }
    }
}

// ---------------------------------------------------------------------------
// RoPE + split fp16 qkv into head-major fp16 q (pre-scaled), k, v
// ---------------------------------------------------------------------------
__global__ __launch_bounds__(64) void rope_f16(
    const __half* __restrict__ qkv, const int* __restrict__ positions)
{
    int bidx = blockIdx.x;
    int h  = bidx % NHEADS;
    int ms = bidx / NHEADS;
    int s  = ms % NS;
    int b  = ms / NS;
    int d  = threadIdx.x;

    const __half* row = qkv + (size_t)ms * NQKV + h * HDIM;
    const float scale = 0.08838834764831845f;   // 1/sqrt(128)

    double pos = (double)positions[ms];
    double inv = exp(-(double)d * (9.210340371976184 / 64.0));
    double ang = pos * inv;
    double sd, cd;
    sincos(ang, &sd, &cd);
    float sn = (float)sd, cs = (float)cd;

    float q1 = __half2float(row[d]),        q2 = __half2float(row[d + 64]);
    float k1 = __half2float(row[NHID + d]), k2 = __half2float(row[NHID + d + 64]);

    size_t o = ((size_t)((b * NHEADS + h)) * NS + s) * HDIM + d;
    g_q16[o]      = __float2half_rn((q1 * cs - q2 * sn) * scale);
    g_q16[o + 64] = __float2half_rn((q2 * cs + q1 * sn) * scale);
    g_k16[o]      = __float2half_rn(k1 * cs - k2 * sn);
    g_k16[o + 64] = __float2half_rn(k2 * cs + k1 * sn);
    g_v16[o]      = row[2 * NHID + d];
    g_v16[o + 64] = row[2 * NHID + d + 64];
}

// ---------------------------------------------------------------------------
// Flash attention, all-fp16 HMMA single-pass. CTA = 128 q-rows, 8 warps,
// 64-wide k chunks, double-buffered cp.async. smem: Q 32K + 2x(K 16K + V 16K).
// ---------------------------------------------------------------------------
#define AQT 128
#define AKT 64
#define AKV 16384
#define ASTG (2 * AKV)                   // K | V
#define ATTN_SMEM (32768 + 2 * ASTG)     // 98304

__global__ __launch_bounds__(256, 1) void attn_mma()
{
    extern __shared__ char smem[];
    const uint32_t sQ = smem_u32(smem);
    const int tid  = threadIdx.x;
    const int lane = tid & 31;
    const int w    = tid >> 5;
    const int qt   = blockIdx.x;
    const int bh   = blockIdx.y;
    const int qs0  = qt * AQT;
    const size_t hb = (size_t)bh * NS * HDIM;

    const int g  = lane >> 2;
    const int t2 = (lane & 3) * 2;
    const int lr = (lane & 7) + ((lane >> 3) & 1) * 8;
    const int lc = lane >> 4;

#pragma unroll
    for (int i = 0; i < 8; i++) {
        int idx = tid + 256 * i;
        int r = idx >> 4, c = idx & 15;
        uint32_t dst = sQ + r * 256 + ((c ^ (r & 7)) << 4);
        cp_async16(dst, g_q16 + hb + (size_t)(qs0 + r) * HDIM + c * 8);
    }
    auto load_kv = [&](int kt, int st) {
        int kc0 = kt * AKT;
        uint32_t sb = sQ + 32768 + st * ASTG;
#pragma unroll
        for (int i = 0; i < 8; i++) {
            int idx = tid + 256 * i;             // 0..2047
            int buf = idx >> 10;                 // 0=K 1=V
            int rem = idx & 1023;
            int r = rem >> 4, c = rem & 15;
            uint32_t dst = sb + buf * AKV + r * 256 + ((c ^ (r & 7)) << 4);
            const __half* src = buf == 0 ? g_k16 : g_v16;
            cp_async16(dst, src + hb + (size_t)(kc0 + r) * HDIM + c * 8);
        }
    };
    load_kv(0, 0);
    CP_COMMIT();

    float oacc[16][4];
#pragma unroll
    for (int i = 0; i < 16; i++)
#pragma unroll
        for (int v = 0; v < 4; v++) oacc[i][v] = 0.f;
    float m0 = -INFINITY, m1 = -INFINITY, l0 = 0.f, l1 = 0.f;

    const int KN = 2 * qt + 2;
    const int row0 = qs0 + w * 16 + g;

    for (int kt = 0; kt < KN; kt++) {
        if (kt + 1 < KN) {
            load_kv(kt + 1, (kt + 1) & 1);
            CP_COMMIT();
            asm volatile("cp.async.wait_group 1;" ::: "memory");
        } else {
            asm volatile("cp.async.wait_group 0;" ::: "memory");
        }
        __syncthreads();

        if (kt * AKT <= qs0 + w * 16 + 15) {
            const uint32_t sK = sQ + 32768 + (kt & 1) * ASTG;
            const uint32_t sV = sK + AKV;

            // ---- S = Q K^T ----
            float sacc[8][4];
#pragma unroll
            for (int nf = 0; nf < 8; nf++)
#pragma unroll
                for (int v = 0; v < 4; v++) sacc[nf][v] = 0.f;

#pragma unroll
            for (int ks = 0; ks < 8; ks++) {
                uint32_t aq[4];
                {
                    int r = w * 16 + lr, c = 2 * ks + lc;
                    ldsm4(aq, sQ + r * 256 + ((c ^ (r & 7)) << 4));
                }
                uint32_t kb4[4][4];
#pragma unroll
                for (int kg = 0; kg < 4; kg++) {
                    int r = kg * 16 + lr, c = 2 * ks + lc;
                    ldsm4(kb4[kg], sK + r * 256 + ((c ^ (r & 7)) << 4));
                }
#pragma unroll
                for (int nf = 0; nf < 8; nf++)
                    mma16816h(sacc[nf], aq, kb4[nf >> 1][nf & 1],
                              kb4[nf >> 1][(nf & 1) + 2]);
            }

            // ---- causal mask (diagonal chunks only) ----
            if (kt * AKT + 63 > qs0 + w * 16) {
#pragma unroll
                for (int nf = 0; nf < 8; nf++) {
                    int cb = kt * AKT + nf * 8 + t2;
                    if (cb     > row0)     sacc[nf][0] = -1e30f;
                    if (cb + 1 > row0)     sacc[nf][1] = -1e30f;
                    if (cb     > row0 + 8) sacc[nf][2] = -1e30f;
                    if (cb + 1 > row0 + 8) sacc[nf][3] = -1e30f;
                }
            }

            // ---- online softmax ----
            float mx0 = -1e30f, mx1 = -1e30f;
#pragma unroll
            for (int nf = 0; nf < 8; nf++) {
                mx0 = fmaxf(mx0, fmaxf(sacc[nf][0], sacc[nf][1]));
                mx1 = fmaxf(mx1, fmaxf(sacc[nf][2], sacc[nf][3]));
            }
            mx0 = fmaxf(mx0, __shfl_xor_sync(0xffffffffu, mx0, 1));
            mx0 = fmaxf(mx0, __shfl_xor_sync(0xffffffffu, mx0, 2));
            mx1 = fmaxf(mx1, __shfl_xor_sync(0xffffffffu, mx1, 1));
            mx1 = fmaxf(mx1, __shfl_xor_sync(0xffffffffu, mx1, 2));

            float nm0 = fmaxf(m0, mx0), nm1 = fmaxf(m1, mx1);
            float cr0 = __expf(m0 - nm0), cr1 = __expf(m1 - nm1);
            m0 = nm0; m1 = nm1;
#pragma unroll
            for (int nf = 0; nf < 16; nf++) {
                oacc[nf][0] *= cr0; oacc[nf][1] *= cr0;
                oacc[nf][2] *= cr1; oacc[nf][3] *= cr1;
            }

            float rs0 = 0.f, rs1 = 0.f;
            uint32_t pf[4][4];
#pragma unroll
            for (int kg = 0; kg < 4; kg++) {
                float p[2][4];
#pragma unroll
                for (int j = 0; j < 2; j++) {
                    int nf = 2 * kg + j;
                    p[j][0] = __expf(sacc[nf][0] - nm0);
                    p[j][1] = __expf(sacc[nf][1] - nm0);
                    p[j][2] = __expf(sacc[nf][2] - nm1);
                    p[j][3] = __expf(sacc[nf][3] - nm1);
                    rs0 += p[j][0] + p[j][1];
                    rs1 += p[j][2] + p[j][3];
                }
                pf[kg][0] = pack_f16(p[0][0], p[0][1]);
                pf[kg][1] = pack_f16(p[0][2], p[0][3]);
                pf[kg][2] = pack_f16(p[1][0], p[1][1]);
                pf[kg][3] = pack_f16(p[1][2], p[1][3]);
            }
            rs0 += __shfl_xor_sync(0xffffffffu, rs0, 1);
            rs0 += __shfl_xor_sync(0xffffffffu, rs0, 2);
            rs1 += __shfl_xor_sync(0xffffffffu, rs1, 1);
            rs1 += __shfl_xor_sync(0xffffffffu, rs1, 2);
            l0 = l0 * cr0 + rs0;
            l1 = l1 * cr1 + rs1;

            // ---- O += P V (single fp16 pass) ----
#pragma unroll
            for (int dg = 0; dg < 8; dg++) {
#pragma unroll
                for (int kg = 0; kg < 4; kg++) {
                    int r = kg * 16 + lr, c = 2 * dg + lc;
                    uint32_t vv[4];
                    ldsm4t(vv, sV + (uint32_t)(r * 256 + ((c ^ (r & 7)) << 4)));
                    mma16816h(oacc[2 * dg],     pf[kg], vv[0], vv[1]);
                    mma16816h(oacc[2 * dg + 1], pf[kg], vv[2], vv[3]);
                }
            }
        }
        __syncthreads();
    }

    // epilogue: normalize, write fp16 into out-proj A buffer
    float inv0 = 1.f / l0, inv1 = 1.f / l1;
    const int b = bh >> 5, h = bh & 31;
    size_t ob0 = (size_t)(b * NS + row0) * NHID + h * HDIM + t2;
    size_t ob1 = ob0 + (size_t)8 * NHID;
#pragma unroll
    for (int nf = 0; nf < 16; nf++) {
        *(uint32_t*)(g_a16 + ob0 + nf * 8) =
            pack_f16(oacc[nf][0] * inv0, oacc[nf][1] * inv0);
        *(uint32_t*)(g_a16 + ob1 + nf * 8) =
            pack_f16(oacc[nf][2] * inv1, oacc[nf][3] * inv1);
    }
}

// ---------------------------------------------------------------------------
// Launch
// ---------------------------------------------------------------------------
extern "C" void kernel_launch(void* const* d_in, const int* in_sizes, int n_in,
                              void* d_out, int out_size)
{
    const float* hs  = (const float*)d_in[0];   // [B,S,H]
    const int*   pos = (const int*)  d_in[1];   // [B,S]
    const float* wp  = (const float*)d_in[2];   // [3H,H]
    const float* wo  = (const float*)d_in[3];   // [H,H]
    float* out = (float*)d_out;                 // [B,S,H]

    __half *qkv, *a16, *b16;
    cudaGetSymbolAddress((void**)&qkv, g_qkv);
    cudaGetSymbolAddress((void**)&a16, g_a16);
    cudaGetSymbolAddress((void**)&b16, g_b16);

    cudaFuncSetAttribute(gemm_f16<__half>, cudaFuncAttributeMaxDynamicSharedMemorySize, GEMM_SMEM);
    cudaFuncSetAttribute(gemm_f16<float>, cudaFuncAttributeMaxDynamicSharedMemorySize, GEMM_SMEM);
    cudaFuncSetAttribute(attn_mma, cudaFuncAttributeMaxDynamicSharedMemorySize, ATTN_SMEM);

    // 1. convert inputs to fp16
    conv_f16<<<(size_t)MTOK * NHID / 1024, 256>>>(hs, a16);
    conv_f16<<<(size_t)NQKV * NHID / 1024, 256>>>(wp, b16);

    // 2. QKV projection (fp16 tensor cores) -> fp16 qkv
    gemm_f16<__half><<<dim3(MTOK / 128, NQKV / 128), 256, GEMM_SMEM>>>(
        a16, b16, qkv, MTOK, NQKV, NHID);

    // 3. RoPE + fp16 head-major split
    rope_f16<<<NB * NS * NHEADS, 64>>>(qkv, pos);

    // 4. Causal flash attention (fp16 HMMA single-pass); fp16 output
    attn_mma<<<dim3(NS / AQT, NB * NHEADS), 256, ATTN_SMEM>>>();

    // 5. output projection -> fp32 result
    conv_f16<<<(size_t)NHID * NHID / 1024, 256>>>(wo, b16);
    gemm_f16<float><<<dim3(MTOK / 128, NHID / 128), 256, GEMM_SMEM>>>(
        a16, b16, out, MTOK, NHID, NHID);
}

// round 10
// speedup vs baseline: 7.8923x; 1.0201x over previous
#include <cuda_runtime.h>
#include <cuda_bf16.h>
#include <cuda_fp16.h>
#include <math.h>
#include <stdint.h>

// Problem constants
#define NB 2
#define NS 2048
#define NHID 4096
#define NHEADS 32
#define HDIM 128
#define NQKV 12288   // 3*NHID
#define MTOK 4096    // NB*NS

// Scratch (device globals: allocation-free per harness rules)
__device__ __half g_qkv[(size_t)MTOK * NQKV];              // 100 MB (fp16); V read in-place
__device__ __half g_q16[(size_t)NB * NHEADS * NS * HDIM];  // head-major, q*scale
__device__ __half g_k16[(size_t)NB * NHEADS * NS * HDIM];
__device__ __half g_a16[(size_t)MTOK * NHID];              // GEMM A (fp16)
__device__ __half g_b16[(size_t)NQKV * NHID];              // GEMM B (fp16)

// ---------------------------------------------------------------------------
// Helpers (baseline PTX, valid on compute_100)
// ---------------------------------------------------------------------------
__device__ __forceinline__ uint32_t smem_u32(const void* p) {
    uint32_t a;
    asm("{ .reg .u64 t; cvta.to.shared.u64 t, %1; cvt.u32.u64 %0, t; }"
        : "=r"(a) : "l"(p));
    return a;
}

__device__ __forceinline__ void cp_async16(uint32_t dst, const void* src) {
    asm volatile("cp.async.cg.shared.global [%0], [%1], 16;" :: "r"(dst), "l"(src));
}
#define CP_COMMIT() asm volatile("cp.async.commit_group;" ::: "memory")

__device__ __forceinline__ void ldsm4(uint32_t* r, uint32_t addr) {
    asm volatile("ldmatrix.sync.aligned.m8n8.x4.shared.b16 {%0,%1,%2,%3}, [%4];"
                 : "=r"(r[0]), "=r"(r[1]), "=r"(r[2]), "=r"(r[3]) : "r"(addr));
}
__device__ __forceinline__ void ldsm4t(uint32_t* r, uint32_t addr) {
    asm volatile("ldmatrix.sync.aligned.m8n8.x4.trans.shared.b16 {%0,%1,%2,%3}, [%4];"
                 : "=r"(r[0]), "=r"(r[1]), "=r"(r[2]), "=r"(r[3]) : "r"(addr));
}

__device__ __forceinline__ void mma16816h(float* c, const uint32_t* a,
                                          uint32_t b0, uint32_t b1) {  // fp16
    asm volatile(
        "mma.sync.aligned.m16n8k16.row.col.f32.f16.f16.f32 "
        "{%0,%1,%2,%3}, {%4,%5,%6,%7}, {%8,%9}, {%0,%1,%2,%3};"
        : "+f"(c[0]), "+f"(c[1]), "+f"(c[2]), "+f"(c[3])
        : "r"(a[0]), "r"(a[1]), "r"(a[2]), "r"(a[3]), "r"(b0), "r"(b1));
}

#define SWZ(x) ((x) ^ (((x) >> 3) & 0x70))

__device__ __forceinline__ uint32_t pack_f16(float x, float y) {
    __half2 t = __floats2half2_rn(x, y);
    return *(uint32_t*)&t;
}

// ---------------------------------------------------------------------------
// convert: fp32 -> fp16
// ---------------------------------------------------------------------------
__global__ __launch_bounds__(256) void conv_f16(
    const float* __restrict__ x, __half* __restrict__ o)
{
    size_t i = ((size_t)blockIdx.x * 256 + threadIdx.x) * 4;
    float4 v = *(const float4*)(x + i);
    uint2 r;
    r.x = pack_f16(v.x, v.y);
    r.y = pack_f16(v.z, v.w);
    *(uint2*)(o + i) = r;
}

// ---------------------------------------------------------------------------
// fp16 single-pass GEMM (NT): C[m,n] = sum_k A[m,k]*B[n,k]
// CTA 128x128, 8 warps (2m x 4n), KTILE=64, 3-stage cp.async, 2 CTAs/SM,
// single barrier per k-iteration (3-stage ring makes the tail sync redundant).
// ---------------------------------------------------------------------------
#define FKT 64
#define FBUF 16384                  // 128 rows x 128 B
#define FSTG (2 * FBUF)             // A + B per stage
#define GEMM_SMEM (3 * FSTG)        // 3 stages: 96 KB

template <typename OutT>
__global__ __launch_bounds__(256, 2) void gemm_f16(
    const __half* __restrict__ A, const __half* __restrict__ B,
    OutT* __restrict__ C, int M, int N, int K)
{
    extern __shared__ char smem[];
    const uint32_t sbase = smem_u32(smem);

    const int tid  = threadIdx.x;
    const int lane = tid & 31;
    const int wid  = tid >> 5;
    const int wm   = wid >> 2;
    const int wn   = wid & 3;
    const int m0   = blockIdx.x * 128;
    const int n0   = blockIdx.y * 128;

    auto load_stage = [&](int kt) {
        const int kk = kt * FKT;
        const uint32_t su = sbase + (kt % 3) * FSTG;
#pragma unroll
        for (int i = 0; i < 8; i++) {
            int c   = tid + 256 * i;        // 0..2047
            int op  = c >> 10;              // 0=A, 1=B
            int rem = c & 1023;
            int r   = rem >> 3;             // row 0..127
            int ch  = rem & 7;              // 16B chunk 0..7
            uint32_t dst = su + op * FBUF + SWZ((uint32_t)(r * 128 + ch * 16));
            const __half* src = op ? B : A;
            size_t gaddr = (size_t)((op ? n0 : m0) + r) * K + kk + ch * 8;
            cp_async16(dst, src + gaddr);
        }
        CP_COMMIT();
    };

    float acc[4][4][4];
#pragma unroll
    for (int i = 0; i < 4; i++)
#pragma unroll
        for (int j = 0; j < 4; j++)
#pragma unroll
            for (int v = 0; v < 4; v++) acc[i][j][v] = 0.f;

    const int KT = K / FKT;
    load_stage(0);
    load_stage(1);

    const int mat  = lane >> 3;
    const int rsub = (mat & 1) * 8 + (lane & 7);
    const int csub = mat >> 1;

    for (int kt = 0; kt < KT; kt++) {
        if (kt + 1 < KT) {
            asm volatile("cp.async.wait_group 1;" ::: "memory");
        } else {
            asm volatile("cp.async.wait_group 0;" ::: "memory");
        }
        __syncthreads();
        // Safe with 3 stages: load target (kt+2)%3 == (kt-1)%3, and every warp
        // passed the barrier above only after finishing compute(kt-1).
        if (kt + 2 < KT) load_stage(kt + 2);

        const uint32_t Ab = sbase + (kt % 3) * FSTG;
        const uint32_t Bb = Ab + FBUF;

#pragma unroll
        for (int ks = 0; ks < 4; ks++) {
            uint32_t af[4][4], bf[2][4];
            const int chh = ks * 2 + csub;
#pragma unroll
            for (int mf = 0; mf < 4; mf++) {
                int r = wm * 64 + mf * 16 + rsub;
                ldsm4(af[mf], Ab + SWZ((uint32_t)(r * 128 + chh * 16)));
            }
#pragma unroll
            for (int nf2 = 0; nf2 < 2; nf2++) {
                int r = wn * 32 + nf2 * 16 + rsub;
                ldsm4(bf[nf2], Bb + SWZ((uint32_t)(r * 128 + chh * 16)));
            }
#pragma unroll
            for (int mf = 0; mf < 4; mf++)
#pragma unroll
                for (int nf = 0; nf < 4; nf++)
                    mma16816h(acc[mf][nf], af[mf],
                              bf[nf >> 1][nf & 1], bf[nf >> 1][(nf & 1) + 2]);
        }
    }

    const int gg = lane >> 2;
    const int tq = lane & 3;
#pragma unroll
    for (int mf = 0; mf < 4; mf++) {
#pragma unroll
        for (int nf = 0; nf < 4; nf++) {
            int row = m0 + wm * 64 + mf * 16 + gg;
            int col = n0 + wn * 32 + nf * 8 + tq * 2;
            if (sizeof(OutT) == 4) {
                *(float2*)((float*)C + (size_t)row * N + col) =
                    make_float2(acc[mf][nf][0], acc[mf][nf][1]);
                *(float2*)((float*)C + (size_t)(row + 8) * N + col) =
                    make_float2(acc[mf][nf][2], acc[mf][nf][3]);
            } else {
                *(uint32_t*)((__half*)C + (size_t)row * N + col) =
                    pack_f16(acc[mf][nf][0], acc[mf][nf][1]);
                *(uint32_t*)((__half*)C + (size_t)(row + 8) * N + col) =
                    pack_f16(acc[mf][nf][2], acc[mf][nf][3]);
            }
        }
    }
}

// ---------------------------------------------------------------------------
// RoPE (fp32 trig) + head-major fp16 q (pre-scaled), k. V stays in g_qkv.
// Angle errors (<~5e-4 rad) perturb only logits: delta_logit/logit_std ≈
// delta_angle, far below fp16-P rounding. 128 threads = 2 (token,head) pairs.
// ---------------------------------------------------------------------------
__global__ __launch_bounds__(128) void rope_f16(
    const __half* __restrict__ qkv, const int* __restrict__ positions)
{
    int t  = threadIdx.x;
    int gi = blockIdx.x * 2 + (t >> 6);   // (b*NS+s)*NHEADS+h
    int d  = t & 63;
    int h  = gi % NHEADS;
    int ms = gi / NHEADS;
    int s  = ms % NS;
    int b  = ms / NS;

    const __half* row = qkv + (size_t)ms * NQKV + h * HDIM;
    const float scale = 0.08838834764831845f;   // 1/sqrt(128)

    float posf = (float)positions[ms];
    float invf = expf(-(float)d * (9.210340371976184f / 64.0f));  // ln(10000)/64
    float sn, cs;
    sincosf(posf * invf, &sn, &cs);

    float q1 = __half2float(row[d]),        q2 = __half2float(row[d + 64]);
    float k1 = __half2float(row[NHID + d]), k2 = __half2float(row[NHID + d + 64]);

    size_t o = ((size_t)((b * NHEADS + h)) * NS + s) * HDIM + d;
    g_q16[o]      = __float2half_rn((q1 * cs - q2 * sn) * scale);
    g_q16[o + 64] = __float2half_rn((q2 * cs + q1 * sn) * scale);
    g_k16[o]      = __float2half_rn(k1 * cs - k2 * sn);
    g_k16[o + 64] = __float2half_rn(k2 * cs + k1 * sn);
}

// ---------------------------------------------------------------------------
// Flash attention, all-fp16 HMMA single-pass. CTA = 128 q-rows, 8 warps,
// 64-wide k chunks, 3-stage cp.async KV pipeline (single sync per chunk).
// V is read directly from g_qkv (row stride NQKV). Heavy q-tiles run first.
// ---------------------------------------------------------------------------
#define AQT 128
#define AKT 64
#define AKV 16384
#define ASTG (2 * AKV)                   // K | V per stage
#define ATTN_SMEM (32768 + 3 * ASTG)     // Q + 3 stages = 131072

__global__ __launch_bounds__(256, 1) void attn_mma()
{
    extern __shared__ char smem[];
    const uint32_t sQ = smem_u32(smem);
    const int tid  = threadIdx.x;
    const int lane = tid & 31;
    const int w    = tid >> 5;
    const int qt   = (int)gridDim.x - 1 - (int)blockIdx.x;  // heavy tiles first
    const int bh   = blockIdx.y;
    const int qs0  = qt * AQT;
    const size_t hb = (size_t)bh * NS * HDIM;
    const int b = bh >> 5, h = bh & 31;

    const int g  = lane >> 2;
    const int t2 = (lane & 3) * 2;
    const int lr = (lane & 7) + ((lane >> 3) & 1) * 8;
    const int lc = lane >> 4;

#pragma unroll
    for (int i = 0; i < 8; i++) {
        int idx = tid + 256 * i;
        int r = idx >> 4, c = idx & 15;
        uint32_t dst = sQ + r * 256 + ((c ^ (r & 7)) << 4);
        cp_async16(dst, g_q16 + hb + (size_t)(qs0 + r) * HDIM + c * 8);
    }
    auto load_kv = [&](int kt) {
        int kc0 = kt * AKT;
        uint32_t sb = sQ + 32768 + (kt % 3) * ASTG;
#pragma unroll
        for (int i = 0; i < 8; i++) {
            int idx = tid + 256 * i;             // 0..2047
            int buf = idx >> 10;                 // 0=K 1=V
            int rem = idx & 1023;
            int r = rem >> 4, c = rem & 15;
            uint32_t dst = sb + buf * AKV + r * 256 + ((c ^ (r & 7)) << 4);
            const void* src = buf == 0
                ? (const void*)(g_k16 + hb + (size_t)(kc0 + r) * HDIM + c * 8)
                : (const void*)(g_qkv + (size_t)(b * NS + kc0 + r) * NQKV
                                + 2 * NHID + h * HDIM + c * 8);
            cp_async16(dst, src);
        }
        CP_COMMIT();
    };

    const int KN = 2 * qt + 2;
    load_kv(0);                                  // group 0 = Q + KV0
    load_kv(1);                                  // group 1 = KV1  (KN >= 2 always)

    float oacc[16][4];
#pragma unroll
    for (int i = 0; i < 16; i++)
#pragma unroll
        for (int v = 0; v < 4; v++) oacc[i][v] = 0.f;
    float m0 = -INFINITY, m1 = -INFINITY, l0 = 0.f, l1 = 0.f;

    const int row0 = qs0 + w * 16 + g;

    for (int kt = 0; kt < KN; kt++) {
        if (kt + 1 < KN) {
            asm volatile("cp.async.wait_group 1;" ::: "memory");
        } else {
            asm volatile("cp.async.wait_group 0;" ::: "memory");
        }
        __syncthreads();
        if (kt + 2 < KN) load_kv(kt + 2);        // safe: stage (kt+2)%3==(kt-1)%3

        if (kt * AKT <= qs0 + w * 16 + 15) {
            const uint32_t sK = sQ + 32768 + (kt % 3) * ASTG;
            const uint32_t sV = sK + AKV;

            // ---- S = Q K^T ----
            float sacc[8][4];
#pragma unroll
            for (int nf = 0; nf < 8; nf++)
#pragma unroll
                for (int v = 0; v < 4; v++) sacc[nf][v] = 0.f;

#pragma unroll
            for (int ks = 0; ks < 8; ks++) {
                uint32_t aq[4];
                {
                    int r = w * 16 + lr, c = 2 * ks + lc;
                    ldsm4(aq, sQ + r * 256 + ((c ^ (r & 7)) << 4));
                }
                uint32_t kb4[4][4];
#pragma unroll
                for (int kg = 0; kg < 4; kg++) {
                    int r = kg * 16 + lr, c = 2 * ks + lc;
                    ldsm4(kb4[kg], sK + r * 256 + ((c ^ (r & 7)) << 4));
                }
#pragma unroll
                for (int nf = 0; nf < 8; nf++)
                    mma16816h(sacc[nf], aq, kb4[nf >> 1][nf & 1],
                              kb4[nf >> 1][(nf & 1) + 2]);
            }

            // ---- causal mask (diagonal chunks only) ----
            if (kt * AKT + 63 > qs0 + w * 16) {
#pragma unroll
                for (int nf = 0; nf < 8; nf++) {
                    int cb = kt * AKT + nf * 8 + t2;
                    if (cb     > row0)     sacc[nf][0] = -1e30f;
                    if (cb + 1 > row0)     sacc[nf][1] = -1e30f;
                    if (cb     > row0 + 8) sacc[nf][2] = -1e30f;
                    if (cb + 1 > row0 + 8) sacc[nf][3] = -1e30f;
                }
            }

            // ---- online softmax ----
            float mx0 = -1e30f, mx1 = -1e30f;
#pragma unroll
            for (int nf = 0; nf < 8; nf++) {
                mx0 = fmaxf(mx0, fmaxf(sacc[nf][0], sacc[nf][1]));
                mx1 = fmaxf(mx1, fmaxf(sacc[nf][2], sacc[nf][3]));
            }
            mx0 = fmaxf(mx0, __shfl_xor_sync(0xffffffffu, mx0, 1));
            mx0 = fmaxf(mx0, __shfl_xor_sync(0xffffffffu, mx0, 2));
            mx1 = fmaxf(mx1, __shfl_xor_sync(0xffffffffu, mx1, 1));
            mx1 = fmaxf(mx1, __shfl_xor_sync(0xffffffffu, mx1, 2));

            float nm0 = fmaxf(m0, mx0), nm1 = fmaxf(m1, mx1);
            float cr0 = __expf(m0 - nm0), cr1 = __expf(m1 - nm1);
            m0 = nm0; m1 = nm1;
#pragma unroll
            for (int nf = 0; nf < 16; nf++) {
                oacc[nf][0] *= cr0; oacc[nf][1] *= cr0;
                oacc[nf][2] *= cr1; oacc[nf][3] *= cr1;
            }

            float rs0 = 0.f, rs1 = 0.f;
            uint32_t pf[4][4];
#pragma unroll
            for (int kg = 0; kg < 4; kg++) {
                float p[2][4];
#pragma unroll
                for (int j = 0; j < 2; j++) {
                    int nf = 2 * kg + j;
                    p[j][0] = __expf(sacc[nf][0] - nm0);
                    p[j][1] = __expf(sacc[nf][1] - nm0);
                    p[j][2] = __expf(sacc[nf][2] - nm1);
                    p[j][3] = __expf(sacc[nf][3] - nm1);
                    rs0 += p[j][0] + p[j][1];
                    rs1 += p[j][2] + p[j][3];
                }
                pf[kg][0] = pack_f16(p[0][0], p[0][1]);
                pf[kg][1] = pack_f16(p[0][2], p[0][3]);
                pf[kg][2] = pack_f16(p[1][0], p[1][1]);
                pf[kg][3] = pack_f16(p[1][2], p[1][3]);
            }
            rs0 += __shfl_xor_sync(0xffffffffu, rs0, 1);
            rs0 += __shfl_xor_sync(0xffffffffu, rs0, 2);
            rs1 += __shfl_xor_sync(0xffffffffu, rs1, 1);
            rs1 += __shfl_xor_sync(0xffffffffu, rs1, 2);
            l0 = l0 * cr0 + rs0;
            l1 = l1 * cr1 + rs1;

            // ---- O += P V (single fp16 pass) ----
#pragma unroll
            for (int dg = 0; dg < 8; dg++) {
#pragma unroll
                for (int kg = 0; kg < 4; kg++) {
                    int r = kg * 16 + lr, c = 2 * dg + lc;
                    uint32_t vv[4];
                    ldsm4t(vv, sV + (uint32_t)(r * 256 + ((c ^ (r & 7)) << 4)));
                    mma16816h(oacc[2 * dg],     pf[kg], vv[0], vv[1]);
                    mma16816h(oacc[2 * dg + 1], pf[kg], vv[2], vv[3]);
                }
            }
        }
        __syncthreads();   // protect current stage from load(kt+3) next iter
    }

    // epilogue: normalize, write fp16 into out-proj A buffer
    float inv0 = 1.f / l0, inv1 = 1.f / l1;
    size_t ob0 = (size_t)(b * NS + row0) * NHID + h * HDIM + t2;
    size_t ob1 = ob0 + (size_t)8 * NHID;
#pragma unroll
    for (int nf = 0; nf < 16; nf++) {
        *(uint32_t*)(g_a16 + ob0 + nf * 8) =
            pack_f16(oacc[nf][0] * inv0, oacc[nf][1] * inv0);
        *(uint32_t*)(g_a16 + ob1 + nf * 8) =
            pack_f16(oacc[nf][2] * inv1, oacc[nf][3] * inv1);
    }
}

// ---------------------------------------------------------------------------
// Launch
// ---------------------------------------------------------------------------
extern "C" void kernel_launch(void* const* d_in, const int* in_sizes, int n_in,
                              void* d_out, int out_size)
{
    const float* hs  = (const float*)d_in[0];   // [B,S,H]
    const int*   pos = (const int*)  d_in[1];   // [B,S]
    const float* wp  = (const float*)d_in[2];   // [3H,H]
    const float* wo  = (const float*)d_in[3];   // [H,H]
    float* out = (float*)d_out;                 // [B,S,H]

    __half *qkv, *a16, *b16;
    cudaGetSymbolAddress((void**)&qkv, g_qkv);
    cudaGetSymbolAddress((void**)&a16, g_a16);
    cudaGetSymbolAddress((void**)&b16, g_b16);

    cudaFuncSetAttribute(gemm_f16<__half>, cudaFuncAttributeMaxDynamicSharedMemorySize, GEMM_SMEM);
    cudaFuncSetAttribute(gemm_f16<float>, cudaFuncAttributeMaxDynamicSharedMemorySize, GEMM_SMEM);
    cudaFuncSetAttribute(attn_mma, cudaFuncAttributeMaxDynamicSharedMemorySize, ATTN_SMEM);

    // 1. convert inputs to fp16
    conv_f16<<<(size_t)MTOK * NHID / 1024, 256>>>(hs, a16);
    conv_f16<<<(size_t)NQKV * NHID / 1024, 256>>>(wp, b16);

    // 2. QKV projection (fp16 tensor cores) -> fp16 qkv
    gemm_f16<__half><<<dim3(MTOK / 128, NQKV / 128), 256, GEMM_SMEM>>>(
        a16, b16, qkv, MTOK, NQKV, NHID);

    // 3. RoPE (fp32 trig) -> head-major q,k; V stays in qkv
    rope_f16<<<NB * NS * NHEADS / 2, 128>>>(qkv, pos);

    // 4. Causal flash attention (fp16 HMMA); fp16 output
    attn_mma<<<dim3(NS / AQT, NB * NHEADS), 256, ATTN_SMEM>>>();

    // 5. output projection -> fp32 result
    conv_f16<<<(size_t)NHID * NHID / 1024, 256>>>(wo, b16);
    gemm_f16<float><<<dim3(MTOK / 128, NHID / 128), 256, GEMM_SMEM>>>(
        a16, b16, out, MTOK, NHID, NHID);
}